// round 1
// baseline (speedup 1.0000x reference)
#include <cuda_runtime.h>

// Problem constants
#define BB   4
#define CC   192
#define C3   576
#define HGT  256
#define WID  256
#define HWS  65536
#define NH   4
#define DD   48
#define NCHUNK 32
#define CHL  (HWS / NCHUNK)   // 2048

// Scratch (device globals: allocation-free per harness rules)
__device__ float g_qkv[(size_t)BB * C3 * HWS];   // 1x1 conv output   (604 MB)
__device__ float g_dw [(size_t)BB * C3 * HWS];   // dwconv output     (604 MB)
__device__ float g_sq [BB * 2 * CC];             // sum-of-squares for q,k rows
__device__ float g_part[(size_t)NCHUNK * BB * NH * DD * DD]; // split-K partials of S
__device__ float g_w2 [BB * CC * CC];            // fused proj_w @ blockdiag(attn)

// ---------------------------------------------------------------------------
// Generic fp32 GEMM: C[M,N] = A[M,K] @ B[K,N], row-major, batched via grid.z.
// BM=64, BN=256, BK=16, 256 threads, 8x8 micro-tile per thread.
// Requires M%64==0, N%256==0, K%16==0 (true for both uses: 576/192 x 65536 x 192).
// ---------------------------------------------------------------------------
__global__ __launch_bounds__(256) void gemm_kernel(
    const float* __restrict__ A, const float* __restrict__ B, float* __restrict__ C,
    int M, int N, int K, long sA, long sB, long sC)
{
    __shared__ float As[16][64];    // stored transposed: As[k][m]
    __shared__ float Bs[16][256];

    const float* Ab = A + (long)blockIdx.z * sA;
    const float* Bb = B + (long)blockIdx.z * sB;
    float*       Cb = C + (long)blockIdx.z * sC;

    const int m0 = blockIdx.y * 64;
    const int n0 = blockIdx.x * 256;
    const int t  = threadIdx.x;
    const int tx = t & 31;          // lane
    const int ty = t >> 5;          // warp id (0..7)
    const int tn = tx * 4;          // this thread's columns: [tn,tn+4) and [tn+128,tn+132)
    const int tm = ty * 8;          // this thread's rows: [tm, tm+8)

    float acc[8][8];
    #pragma unroll
    for (int i = 0; i < 8; i++)
        #pragma unroll
        for (int j = 0; j < 8; j++) acc[i][j] = 0.f;

    for (int k0 = 0; k0 < K; k0 += 16) {
        // Load A tile 64x16 (one float4 per thread), transpose into As
        {
            int m  = t >> 2;
            int kk = (t & 3) << 2;
            float4 a4 = *(const float4*)(Ab + (long)(m0 + m) * K + k0 + kk);
            As[kk + 0][m] = a4.x;
            As[kk + 1][m] = a4.y;
            As[kk + 2][m] = a4.z;
            As[kk + 3][m] = a4.w;
        }
        // Load B tile 16x256 (4 float4 per thread), coalesced rows
        {
            int n4 = (t & 63) << 2;
            int kr = t >> 6;        // 0..3
            #pragma unroll
            for (int i = 0; i < 4; i++) {
                int kk = kr + i * 4;
                *(float4*)&Bs[kk][n4] = *(const float4*)(Bb + (long)(k0 + kk) * N + n0 + n4);
            }
        }
        __syncthreads();

        #pragma unroll
        for (int kk = 0; kk < 16; kk++) {
            float a[8], bv[8];
            *(float4*)&a[0]  = *(const float4*)&As[kk][tm];
            *(float4*)&a[4]  = *(const float4*)&As[kk][tm + 4];
            *(float4*)&bv[0] = *(const float4*)&Bs[kk][tn];
            *(float4*)&bv[4] = *(const float4*)&Bs[kk][tn + 128];
            #pragma unroll
            for (int i = 0; i < 8; i++)
                #pragma unroll
                for (int j = 0; j < 8; j++)
                    acc[i][j] += a[i] * bv[j];
        }
        __syncthreads();
    }

    #pragma unroll
    for (int i = 0; i < 8; i++) {
        float* cp = Cb + (long)(m0 + tm + i) * N + n0;
        float4 v0 = make_float4(acc[i][0], acc[i][1], acc[i][2], acc[i][3]);
        float4 v1 = make_float4(acc[i][4], acc[i][5], acc[i][6], acc[i][7]);
        *(float4*)(cp + tn)       = v0;
        *(float4*)(cp + tn + 128) = v1;
    }
}

// ---------------------------------------------------------------------------
// Depthwise 3x3 conv, padding SAME. One output pixel per thread.
// grid: (WID/32, HGT/8, BB*C3), block (32,8)
// ---------------------------------------------------------------------------
__global__ __launch_bounds__(256) void dwconv_kernel(const float* __restrict__ w)
{
    const int bc = blockIdx.z;          // b*576 + c
    const int c  = bc % C3;
    const float* plane = g_qkv + (size_t)bc * HWS;
    float*       op    = g_dw  + (size_t)bc * HWS;

    float wr[9];
    #pragma unroll
    for (int i = 0; i < 9; i++) wr[i] = w[c * 9 + i];

    const int x = blockIdx.x * 32 + threadIdx.x;
    const int y = blockIdx.y * 8  + threadIdx.y;

    float acc = 0.f;
    #pragma unroll
    for (int dy = -1; dy <= 1; dy++) {
        int yy = y + dy;
        if (yy >= 0 && yy < HGT) {
            const float* row = plane + yy * WID;
            #pragma unroll
            for (int dx = -1; dx <= 1; dx++) {
                int xx = x + dx;
                if (xx >= 0 && xx < WID)
                    acc += wr[(dy + 1) * 3 + (dx + 1)] * row[xx];
            }
        }
    }
    op[y * WID + x] = acc;
}

// ---------------------------------------------------------------------------
// Sum of squares per (b, channel) plane for q (c 0..191) and k (c 192..383).
// grid: BB*384 blocks of 256.
// ---------------------------------------------------------------------------
__global__ __launch_bounds__(256) void sumsq_kernel()
{
    const int idx = blockIdx.x;
    const int b = idx / (2 * CC);
    const int c = idx % (2 * CC);
    const float4* p = (const float4*)(g_dw + ((size_t)b * C3 + c) * HWS);

    float s = 0.f;
    for (int i = threadIdx.x; i < HWS / 4; i += 256) {
        float4 v = p[i];
        s += v.x * v.x + v.y * v.y + v.z * v.z + v.w * v.w;
    }
    __shared__ float red[256];
    red[threadIdx.x] = s;
    __syncthreads();
    #pragma unroll
    for (int off = 128; off > 0; off >>= 1) {
        if (threadIdx.x < off) red[threadIdx.x] += red[threadIdx.x + off];
        __syncthreads();
    }
    if (threadIdx.x == 0) g_sq[idx] = red[0];
}

// ---------------------------------------------------------------------------
// Split-K partials of S = Q @ K^T per (b,h). grid (NCHUNK, BB*NH), block 256.
// Each thread owns a 3x3 patch of the 48x48 output.
// ---------------------------------------------------------------------------
__global__ __launch_bounds__(256) void qk_partial_kernel()
{
    const int chunk = blockIdx.x;
    const int bh    = blockIdx.y;
    const int b  = bh >> 2;
    const int hh = bh & 3;

    const float* qb = g_dw + ((size_t)b * C3 + hh * DD) * HWS + (size_t)chunk * CHL;
    const float* kb = qb + (size_t)CC * HWS;   // k is channels +192

    __shared__ float qs[DD][33];
    __shared__ float ks[DD][33];

    const int t  = threadIdx.x;
    const int td = (t >> 4) * 3;   // 0..45
    const int te = (t & 15) * 3;

    float acc[3][3] = {{0.f, 0.f, 0.f}, {0.f, 0.f, 0.f}, {0.f, 0.f, 0.f}};

    for (int n0 = 0; n0 < CHL; n0 += 32) {
        #pragma unroll
        for (int i = 0; i < 6; i++) {
            int idx = t + i * 256;       // 0..1535 = 48*32
            int cc = idx >> 5, nn = idx & 31;
            qs[cc][nn] = qb[(size_t)cc * HWS + n0 + nn];
            ks[cc][nn] = kb[(size_t)cc * HWS + n0 + nn];
        }
        __syncthreads();
        #pragma unroll 8
        for (int nn = 0; nn < 32; nn++) {
            float qv[3], kv[3];
            qv[0] = qs[td][nn]; qv[1] = qs[td + 1][nn]; qv[2] = qs[td + 2][nn];
            kv[0] = ks[te][nn]; kv[1] = ks[te + 1][nn]; kv[2] = ks[te + 2][nn];
            #pragma unroll
            for (int i = 0; i < 3; i++)
                #pragma unroll
                for (int j = 0; j < 3; j++)
                    acc[i][j] += qv[i] * kv[j];
        }
        __syncthreads();
    }

    float* dst = g_part + ((size_t)chunk * (BB * NH) + bh) * (DD * DD);
    #pragma unroll
    for (int i = 0; i < 3; i++)
        #pragma unroll
        for (int j = 0; j < 3; j++)
            dst[(td + i) * DD + te + j] = acc[i][j];
}

// ---------------------------------------------------------------------------
// Reduce partials -> scale by temp/(||q|| ||k||) -> softmax -> build
// W2[b][o][h*48+e] = sum_d proj_w[o][h*48+d] * attn[d][e].
// grid BB*NH, block 192 (one thread per output row o).
// ---------------------------------------------------------------------------
__global__ __launch_bounds__(192) void softmax_w2_kernel(
    const float* __restrict__ temp, const float* __restrict__ projw)
{
    const int bh = blockIdx.x;
    const int b  = bh >> 2;
    const int hh = bh & 3;
    const int t  = threadIdx.x;

    __shared__ float S[DD][DD];
    __shared__ float nq[DD], nk[DD];

    // deterministic fixed-order reduce of split-K partials
    for (int i = t; i < DD * DD; i += 192) {
        float s = 0.f;
        for (int ch = 0; ch < NCHUNK; ch++)
            s += g_part[((size_t)ch * (BB * NH) + bh) * (DD * DD) + i];
        S[i / DD][i % DD] = s;
    }
    if (t < DD) {
        nq[t] = fmaxf(sqrtf(g_sq[b * 2 * CC + hh * DD + t]),      1e-12f);
        nk[t] = fmaxf(sqrtf(g_sq[b * 2 * CC + CC + hh * DD + t]), 1e-12f);
    }
    __syncthreads();

    const float tmp = temp[hh];
    for (int i = t; i < DD * DD; i += 192) {
        int d = i / DD, e = i % DD;
        S[d][e] = S[d][e] * tmp / (nq[d] * nk[e]);
    }
    __syncthreads();

    // row softmax (one thread per row)
    if (t < DD) {
        float mx = -1e30f;
        #pragma unroll
        for (int e = 0; e < DD; e++) mx = fmaxf(mx, S[t][e]);
        float sum = 0.f;
        #pragma unroll
        for (int e = 0; e < DD; e++) { float v = expf(S[t][e] - mx); S[t][e] = v; sum += v; }
        float inv = 1.f / sum;
        #pragma unroll
        for (int e = 0; e < DD; e++) S[t][e] *= inv;
    }
    __syncthreads();

    // W2 slice for this head: [192 x 48]
    const int o = t;
    float pr[DD];
    #pragma unroll
    for (int d = 0; d < DD; d++) pr[d] = projw[o * CC + hh * DD + d];
    #pragma unroll 4
    for (int e = 0; e < DD; e++) {
        float s = 0.f;
        #pragma unroll
        for (int d = 0; d < DD; d++) s += pr[d] * S[d][e];
        g_w2[((size_t)b * CC + o) * CC + hh * DD + e] = s;
    }
}

// ---------------------------------------------------------------------------
extern "C" void kernel_launch(void* const* d_in, const int* in_sizes, int n_in,
                              void* d_out, int out_size)
{
    const float* x      = (const float*)d_in[0];   // [4,192,256,256]
    const float* qkv_w  = (const float*)d_in[1];   // [576,192]
    const float* dw_w   = (const float*)d_in[2];   // [576,1,3,3]
    const float* temp   = (const float*)d_in[3];   // [4,1,1]
    const float* proj_w = (const float*)d_in[4];   // [192,192]
    float* out = (float*)d_out;                    // [4,192,256,256]

    float *qkv_buf, *dw_buf, *w2_buf;
    cudaGetSymbolAddress((void**)&qkv_buf, g_qkv);
    cudaGetSymbolAddress((void**)&dw_buf,  g_dw);
    cudaGetSymbolAddress((void**)&w2_buf,  g_w2);

    // 1) qkv 1x1 conv: [576,192] @ [192,65536] per batch
    gemm_kernel<<<dim3(HWS / 256, C3 / 64, BB), 256>>>(
        qkv_w, x, qkv_buf, C3, HWS, CC,
        0L, (long)CC * HWS, (long)C3 * HWS);

    // 2) depthwise 3x3
    dwconv_kernel<<<dim3(WID / 32, HGT / 8, BB * C3), dim3(32, 8)>>>(dw_w);

    // 3) ||q||^2, ||k||^2 per channel plane
    sumsq_kernel<<<BB * 2 * CC, 256>>>();

    // 4) split-K S = Q K^T partials
    qk_partial_kernel<<<dim3(NCHUNK, BB * NH), 256>>>();

    // 5) reduce + scale + softmax + W2 = proj_w @ blockdiag(attn)
    softmax_w2_kernel<<<BB * NH, 192>>>(temp, proj_w);

    // 6) fused (attn @ v) + proj: out = W2[192,192] @ v[192,65536] per batch
    gemm_kernel<<<dim3(HWS / 256, CC / 64, BB), 256>>>(
        w2_buf, dw_buf + (size_t)2 * CC * HWS, out, CC, HWS, CC,
        (long)CC * CC, (long)C3 * HWS, (long)CC * HWS);
}

// round 2
// speedup vs baseline: 1.4661x; 1.4661x over previous
#include <cuda_runtime.h>

// Problem constants
#define BB   4
#define CC   192
#define C3   576
#define HGT  256
#define WID  256
#define HWS  65536
#define NH   4
#define DD   48
#define NCHUNK 32
#define CHL  (HWS / NCHUNK)   // 2048

// Scratch (device globals: allocation-free per harness rules)
__device__ float g_qkv[(size_t)BB * C3 * HWS];   // 1x1 conv output
__device__ float g_dw [(size_t)BB * C3 * HWS];   // dwconv output
__device__ float g_sq [BB * 2 * CC];             // sum-of-squares for q,k rows
__device__ float g_part[(size_t)NCHUNK * BB * NH * DD * DD]; // split-K partials of S
__device__ float g_w2 [BB * CC * CC];            // fused proj_w @ blockdiag(attn)

// ---------------------------------------------------------------------------
// tf32 helpers
// ---------------------------------------------------------------------------
__device__ __forceinline__ unsigned f2tf32(float f) {
    unsigned u;
    asm("cvt.rna.tf32.f32 %0, %1;" : "=r"(u) : "f"(f));
    return u;
}

__device__ __forceinline__ void mma_tf32(float c[4], const unsigned a[4], const unsigned b[2]) {
    asm volatile(
        "mma.sync.aligned.m16n8k8.row.col.f32.tf32.tf32.f32 "
        "{%0,%1,%2,%3}, {%4,%5,%6,%7}, {%8,%9}, {%0,%1,%2,%3};"
        : "+f"(c[0]), "+f"(c[1]), "+f"(c[2]), "+f"(c[3])
        : "r"(a[0]), "r"(a[1]), "r"(a[2]), "r"(a[3]), "r"(b[0]), "r"(b[1]));
}

// ---------------------------------------------------------------------------
// tf32 tensor-core GEMM: C[M,N] = A[M,K] @ B[K,N], row-major, batch via grid.z
// BM=64, BN=256, BK=16, 256 threads (8 warps of 32x64).
// Requires M%64==0, N%256==0, K%16==0. grid = (M/64, N/256, batch) — m fastest
// so m-blocks sharing a B n-strip are co-resident (B served from L2).
// ---------------------------------------------------------------------------
__global__ __launch_bounds__(256, 2) void gemm_tf32_kernel(
    const float* __restrict__ A, const float* __restrict__ B, float* __restrict__ C,
    int M, int N, int K, long sA, long sB, long sC)
{
    __shared__ unsigned As[16][64 + 4];    // [k][m], stride 68 (== 4 mod 32)
    __shared__ unsigned Bs[16][256 + 4];   // [k][n], stride 260 (== 4 mod 32)

    const float* Ab = A + (long)blockIdx.z * sA;
    const float* Bb = B + (long)blockIdx.z * sB;
    float*       Cb = C + (long)blockIdx.z * sC;

    const int m0 = blockIdx.x * 64;
    const int n0 = blockIdx.y * 256;
    const int t    = threadIdx.x;
    const int lane = t & 31;
    const int wid  = t >> 5;
    const int wm   = (wid & 1) * 32;       // warp m offset within block tile
    const int wn   = (wid >> 1) * 64;      // warp n offset
    const int g    = lane >> 2;            // 0..7
    const int tg   = lane & 3;             // 0..3

    float acc[2][8][4];
    #pragma unroll
    for (int mt = 0; mt < 2; mt++)
        #pragma unroll
        for (int nt = 0; nt < 8; nt++)
            #pragma unroll
            for (int i = 0; i < 4; i++) acc[mt][nt][i] = 0.f;

    // per-thread load coordinates
    const int am  = t >> 2;                // 0..63
    const int ak  = (t & 3) << 2;          // 0,4,8,12
    const int bn4 = (t & 63) << 2;         // 0..252
    const int bkr = t >> 6;                // 0..3

    for (int k0 = 0; k0 < K; k0 += 16) {
        // A tile 64x16 -> As[k][m], tf32-rounded
        {
            float4 a4 = *(const float4*)(Ab + (long)(m0 + am) * K + k0 + ak);
            As[ak + 0][am] = f2tf32(a4.x);
            As[ak + 1][am] = f2tf32(a4.y);
            As[ak + 2][am] = f2tf32(a4.z);
            As[ak + 3][am] = f2tf32(a4.w);
        }
        // B tile 16x256 -> Bs[k][n], tf32-rounded, coalesced rows
        #pragma unroll
        for (int i = 0; i < 4; i++) {
            int kk = bkr + i * 4;
            float4 b4 = *(const float4*)(Bb + (long)(k0 + kk) * N + n0 + bn4);
            uint4 u;
            u.x = f2tf32(b4.x); u.y = f2tf32(b4.y);
            u.z = f2tf32(b4.z); u.w = f2tf32(b4.w);
            *(uint4*)&Bs[kk][bn4] = u;
        }
        __syncthreads();

        #pragma unroll
        for (int s = 0; s < 16; s += 8) {
            unsigned af[2][4], bf[8][2];
            #pragma unroll
            for (int mt = 0; mt < 2; mt++) {
                int mb = wm + mt * 16 + g;
                af[mt][0] = As[s + tg][mb];
                af[mt][1] = As[s + tg][mb + 8];
                af[mt][2] = As[s + tg + 4][mb];
                af[mt][3] = As[s + tg + 4][mb + 8];
            }
            #pragma unroll
            for (int nt = 0; nt < 8; nt++) {
                int nb = wn + nt * 8 + g;
                bf[nt][0] = Bs[s + tg][nb];
                bf[nt][1] = Bs[s + tg + 4][nb];
            }
            #pragma unroll
            for (int mt = 0; mt < 2; mt++)
                #pragma unroll
                for (int nt = 0; nt < 8; nt++)
                    mma_tf32(acc[mt][nt], af[mt], bf[nt]);
        }
        __syncthreads();
    }

    // store: c0,c1 at (row g, cols 2tg,2tg+1); c2,c3 at (row g+8)
    #pragma unroll
    for (int mt = 0; mt < 2; mt++) {
        #pragma unroll
        for (int nt = 0; nt < 8; nt++) {
            int row = m0 + wm + mt * 16 + g;
            int col = n0 + wn + nt * 8 + 2 * tg;
            float2 v0 = make_float2(acc[mt][nt][0], acc[mt][nt][1]);
            float2 v1 = make_float2(acc[mt][nt][2], acc[mt][nt][3]);
            *(float2*)(Cb + (long)row * N + col)       = v0;
            *(float2*)(Cb + (long)(row + 8) * N + col) = v1;
        }
    }
}

// ---------------------------------------------------------------------------
// Depthwise 3x3 conv, padding SAME. One output pixel per thread.
// ---------------------------------------------------------------------------
__global__ __launch_bounds__(256) void dwconv_kernel(const float* __restrict__ w)
{
    const int bc = blockIdx.z;          // b*576 + c
    const int c  = bc % C3;
    const float* plane = g_qkv + (size_t)bc * HWS;
    float*       op    = g_dw  + (size_t)bc * HWS;

    float wr[9];
    #pragma unroll
    for (int i = 0; i < 9; i++) wr[i] = w[c * 9 + i];

    const int x = blockIdx.x * 32 + threadIdx.x;
    const int y = blockIdx.y * 8  + threadIdx.y;

    float acc = 0.f;
    #pragma unroll
    for (int dy = -1; dy <= 1; dy++) {
        int yy = y + dy;
        if (yy >= 0 && yy < HGT) {
            const float* row = plane + yy * WID;
            #pragma unroll
            for (int dx = -1; dx <= 1; dx++) {
                int xx = x + dx;
                if (xx >= 0 && xx < WID)
                    acc += wr[(dy + 1) * 3 + (dx + 1)] * row[xx];
            }
        }
    }
    op[y * WID + x] = acc;
}

// ---------------------------------------------------------------------------
// Sum of squares per (b, channel) plane for q (c 0..191) and k (c 192..383).
// ---------------------------------------------------------------------------
__global__ __launch_bounds__(256) void sumsq_kernel()
{
    const int idx = blockIdx.x;
    const int b = idx / (2 * CC);
    const int c = idx % (2 * CC);
    const float4* p = (const float4*)(g_dw + ((size_t)b * C3 + c) * HWS);

    float s = 0.f;
    for (int i = threadIdx.x; i < HWS / 4; i += 256) {
        float4 v = p[i];
        s += v.x * v.x + v.y * v.y + v.z * v.z + v.w * v.w;
    }
    __shared__ float red[256];
    red[threadIdx.x] = s;
    __syncthreads();
    #pragma unroll
    for (int off = 128; off > 0; off >>= 1) {
        if (threadIdx.x < off) red[threadIdx.x] += red[threadIdx.x + off];
        __syncthreads();
    }
    if (threadIdx.x == 0) g_sq[idx] = red[0];
}

// ---------------------------------------------------------------------------
// Split-K partials of S = Q @ K^T per (b,h). grid (NCHUNK, BB*NH), block 256.
// ---------------------------------------------------------------------------
__global__ __launch_bounds__(256) void qk_partial_kernel()
{
    const int chunk = blockIdx.x;
    const int bh    = blockIdx.y;
    const int b  = bh >> 2;
    const int hh = bh & 3;

    const float* qb = g_dw + ((size_t)b * C3 + hh * DD) * HWS + (size_t)chunk * CHL;
    const float* kb = qb + (size_t)CC * HWS;   // k is channels +192

    __shared__ float qs[DD][33];
    __shared__ float ks[DD][33];

    const int t  = threadIdx.x;
    const int td = (t >> 4) * 3;   // 0..45
    const int te = (t & 15) * 3;

    float acc[3][3] = {{0.f, 0.f, 0.f}, {0.f, 0.f, 0.f}, {0.f, 0.f, 0.f}};

    for (int n0 = 0; n0 < CHL; n0 += 32) {
        #pragma unroll
        for (int i = 0; i < 6; i++) {
            int idx = t + i * 256;       // 0..1535 = 48*32
            int cc = idx >> 5, nn = idx & 31;
            qs[cc][nn] = qb[(size_t)cc * HWS + n0 + nn];
            ks[cc][nn] = kb[(size_t)cc * HWS + n0 + nn];
        }
        __syncthreads();
        #pragma unroll 8
        for (int nn = 0; nn < 32; nn++) {
            float qv[3], kv[3];
            qv[0] = qs[td][nn]; qv[1] = qs[td + 1][nn]; qv[2] = qs[td + 2][nn];
            kv[0] = ks[te][nn]; kv[1] = ks[te + 1][nn]; kv[2] = ks[te + 2][nn];
            #pragma unroll
            for (int i = 0; i < 3; i++)
                #pragma unroll
                for (int j = 0; j < 3; j++)
                    acc[i][j] += qv[i] * kv[j];
        }
        __syncthreads();
    }

    float* dst = g_part + ((size_t)chunk * (BB * NH) + bh) * (DD * DD);
    #pragma unroll
    for (int i = 0; i < 3; i++)
        #pragma unroll
        for (int j = 0; j < 3; j++)
            dst[(td + i) * DD + te + j] = acc[i][j];
}

// ---------------------------------------------------------------------------
// Reduce partials -> scale by temp/(||q|| ||k||) -> softmax -> build
// W2[b][o][h*48+e] = sum_d proj_w[o][h*48+d] * attn[d][e].
// ---------------------------------------------------------------------------
__global__ __launch_bounds__(192) void softmax_w2_kernel(
    const float* __restrict__ temp, const float* __restrict__ projw)
{
    const int bh = blockIdx.x;
    const int b  = bh >> 2;
    const int hh = bh & 3;
    const int t  = threadIdx.x;

    __shared__ float S[DD][DD];
    __shared__ float nq[DD], nk[DD];

    for (int i = t; i < DD * DD; i += 192) {
        float s = 0.f;
        for (int ch = 0; ch < NCHUNK; ch++)
            s += g_part[((size_t)ch * (BB * NH) + bh) * (DD * DD) + i];
        S[i / DD][i % DD] = s;
    }
    if (t < DD) {
        nq[t] = fmaxf(sqrtf(g_sq[b * 2 * CC + hh * DD + t]),      1e-12f);
        nk[t] = fmaxf(sqrtf(g_sq[b * 2 * CC + CC + hh * DD + t]), 1e-12f);
    }
    __syncthreads();

    const float tmp = temp[hh];
    for (int i = t; i < DD * DD; i += 192) {
        int d = i / DD, e = i % DD;
        S[d][e] = S[d][e] * tmp / (nq[d] * nk[e]);
    }
    __syncthreads();

    if (t < DD) {
        float mx = -1e30f;
        #pragma unroll
        for (int e = 0; e < DD; e++) mx = fmaxf(mx, S[t][e]);
        float sum = 0.f;
        #pragma unroll
        for (int e = 0; e < DD; e++) { float v = expf(S[t][e] - mx); S[t][e] = v; sum += v; }
        float inv = 1.f / sum;
        #pragma unroll
        for (int e = 0; e < DD; e++) S[t][e] *= inv;
    }
    __syncthreads();

    const int o = t;
    float pr[DD];
    #pragma unroll
    for (int d = 0; d < DD; d++) pr[d] = projw[o * CC + hh * DD + d];
    #pragma unroll 4
    for (int e = 0; e < DD; e++) {
        float s = 0.f;
        #pragma unroll
        for (int d = 0; d < DD; d++) s += pr[d] * S[d][e];
        g_w2[((size_t)b * CC + o) * CC + hh * DD + e] = s;
    }
}

// ---------------------------------------------------------------------------
extern "C" void kernel_launch(void* const* d_in, const int* in_sizes, int n_in,
                              void* d_out, int out_size)
{
    const float* x      = (const float*)d_in[0];   // [4,192,256,256]
    const float* qkv_w  = (const float*)d_in[1];   // [576,192]
    const float* dw_w   = (const float*)d_in[2];   // [576,1,3,3]
    const float* temp   = (const float*)d_in[3];   // [4,1,1]
    const float* proj_w = (const float*)d_in[4];   // [192,192]
    float* out = (float*)d_out;                    // [4,192,256,256]

    float *qkv_buf, *dw_buf, *w2_buf;
    cudaGetSymbolAddress((void**)&qkv_buf, g_qkv);
    cudaGetSymbolAddress((void**)&dw_buf,  g_dw);
    cudaGetSymbolAddress((void**)&w2_buf,  g_w2);

    // 1) qkv 1x1 conv: [576,192] @ [192,65536] per batch  (tf32 tensor cores)
    gemm_tf32_kernel<<<dim3(C3 / 64, HWS / 256, BB), 256>>>(
        qkv_w, x, qkv_buf, C3, HWS, CC,
        0L, (long)CC * HWS, (long)C3 * HWS);

    // 2) depthwise 3x3
    dwconv_kernel<<<dim3(WID / 32, HGT / 8, BB * C3), dim3(32, 8)>>>(dw_w);

    // 3) ||q||^2, ||k||^2 per channel plane
    sumsq_kernel<<<BB * 2 * CC, 256>>>();

    // 4) split-K S = Q K^T partials
    qk_partial_kernel<<<dim3(NCHUNK, BB * NH), 256>>>();

    // 5) reduce + scale + softmax + W2 = proj_w @ blockdiag(attn)
    softmax_w2_kernel<<<BB * NH, 192>>>(temp, proj_w);

    // 6) fused (attn @ v) + proj: out = W2[192,192] @ v[192,65536] per batch
    gemm_tf32_kernel<<<dim3(CC / 64, HWS / 256, BB), 256>>>(
        w2_buf, dw_buf + (size_t)2 * CC * HWS, out, CC, HWS, CC,
        (long)CC * CC, (long)C3 * HWS, (long)CC * HWS);
}

// round 3
// speedup vs baseline: 1.9104x; 1.3031x over previous
#include <cuda_runtime.h>

// Problem constants
#define BB   4
#define CC   192
#define C3   576
#define HGT  256
#define WID  256
#define HWS  65536
#define NH   4
#define DD   48
#define NCHUNK 32
#define CHL  (HWS / NCHUNK)   // 2048

// Scratch (device globals: allocation-free per harness rules)
__device__ float g_qkv[(size_t)BB * C3 * HWS];   // 1x1 conv output
__device__ float g_dw [(size_t)BB * C3 * HWS];   // dwconv output
__device__ float g_sqp[BB * C3][32];             // per-block sumsq partials (q,k only)
__device__ float g_sq [BB * 2 * CC];             // sum-of-squares for q,k channels
__device__ float g_part[(size_t)NCHUNK * BB * NH * DD * DD]; // split-K partials of S
__device__ float g_w2 [BB * CC * CC];            // fused proj_w @ blockdiag(attn)

// ---------------------------------------------------------------------------
// tf32 helpers
// ---------------------------------------------------------------------------
__device__ __forceinline__ unsigned f2tf32(float f) {
    unsigned u;
    asm("cvt.rna.tf32.f32 %0, %1;" : "=r"(u) : "f"(f));
    return u;
}

__device__ __forceinline__ void mma_tf32(float c[4], const unsigned a[4], const unsigned b[2]) {
    asm volatile(
        "mma.sync.aligned.m16n8k8.row.col.f32.tf32.tf32.f32 "
        "{%0,%1,%2,%3}, {%4,%5,%6,%7}, {%8,%9}, {%0,%1,%2,%3};"
        : "+f"(c[0]), "+f"(c[1]), "+f"(c[2]), "+f"(c[3])
        : "r"(a[0]), "r"(a[1]), "r"(a[2]), "r"(a[3]), "r"(b[0]), "r"(b[1]));
}

// ---------------------------------------------------------------------------
// tf32 tensor-core GEMM: C[M,N] = A[M,K] @ B[K,N], row-major, batch via grid.z
// BM=64, BN=256, BK=16, 256 threads (8 warps of 32x64).
// ---------------------------------------------------------------------------
__global__ __launch_bounds__(256, 2) void gemm_tf32_kernel(
    const float* __restrict__ A, const float* __restrict__ B, float* __restrict__ C,
    int M, int N, int K, long sA, long sB, long sC)
{
    __shared__ unsigned As[16][64 + 4];
    __shared__ unsigned Bs[16][256 + 4];

    const float* Ab = A + (long)blockIdx.z * sA;
    const float* Bb = B + (long)blockIdx.z * sB;
    float*       Cb = C + (long)blockIdx.z * sC;

    const int m0 = blockIdx.x * 64;
    const int n0 = blockIdx.y * 256;
    const int t    = threadIdx.x;
    const int lane = t & 31;
    const int wid  = t >> 5;
    const int wm   = (wid & 1) * 32;
    const int wn   = (wid >> 1) * 64;
    const int g    = lane >> 2;
    const int tg   = lane & 3;

    float acc[2][8][4];
    #pragma unroll
    for (int mt = 0; mt < 2; mt++)
        #pragma unroll
        for (int nt = 0; nt < 8; nt++)
            #pragma unroll
            for (int i = 0; i < 4; i++) acc[mt][nt][i] = 0.f;

    const int am  = t >> 2;
    const int ak  = (t & 3) << 2;
    const int bn4 = (t & 63) << 2;
    const int bkr = t >> 6;

    for (int k0 = 0; k0 < K; k0 += 16) {
        {
            float4 a4 = *(const float4*)(Ab + (long)(m0 + am) * K + k0 + ak);
            As[ak + 0][am] = f2tf32(a4.x);
            As[ak + 1][am] = f2tf32(a4.y);
            As[ak + 2][am] = f2tf32(a4.z);
            As[ak + 3][am] = f2tf32(a4.w);
        }
        #pragma unroll
        for (int i = 0; i < 4; i++) {
            int kk = bkr + i * 4;
            float4 b4 = *(const float4*)(Bb + (long)(k0 + kk) * N + n0 + bn4);
            uint4 u;
            u.x = f2tf32(b4.x); u.y = f2tf32(b4.y);
            u.z = f2tf32(b4.z); u.w = f2tf32(b4.w);
            *(uint4*)&Bs[kk][bn4] = u;
        }
        __syncthreads();

        #pragma unroll
        for (int s = 0; s < 16; s += 8) {
            unsigned af[2][4], bf[8][2];
            #pragma unroll
            for (int mt = 0; mt < 2; mt++) {
                int mb = wm + mt * 16 + g;
                af[mt][0] = As[s + tg][mb];
                af[mt][1] = As[s + tg][mb + 8];
                af[mt][2] = As[s + tg + 4][mb];
                af[mt][3] = As[s + tg + 4][mb + 8];
            }
            #pragma unroll
            for (int nt = 0; nt < 8; nt++) {
                int nb = wn + nt * 8 + g;
                bf[nt][0] = Bs[s + tg][nb];
                bf[nt][1] = Bs[s + tg + 4][nb];
            }
            #pragma unroll
            for (int mt = 0; mt < 2; mt++)
                #pragma unroll
                for (int nt = 0; nt < 8; nt++)
                    mma_tf32(acc[mt][nt], af[mt], bf[nt]);
        }
        __syncthreads();
    }

    #pragma unroll
    for (int mt = 0; mt < 2; mt++) {
        #pragma unroll
        for (int nt = 0; nt < 8; nt++) {
            int row = m0 + wm + mt * 16 + g;
            int col = n0 + wn + nt * 8 + 2 * tg;
            float2 v0 = make_float2(acc[mt][nt][0], acc[mt][nt][1]);
            float2 v1 = make_float2(acc[mt][nt][2], acc[mt][nt][3]);
            *(float2*)(Cb + (long)row * N + col)       = v0;
            *(float2*)(Cb + (long)(row + 8) * N + col) = v1;
        }
    }
}

// ---------------------------------------------------------------------------
// Depthwise 3x3 conv v2: 8 outputs per thread (vertical sliding window).
// block (64,4) -> tile 64 wide x 32 rows. grid (4, 8, BB*C3).
// Also accumulates per-block sum-of-squares partials for q,k channels.
// ---------------------------------------------------------------------------
__global__ __launch_bounds__(256) void dwconv_kernel(const float* __restrict__ w)
{
    const int bc = blockIdx.z;          // b*576 + c
    const int c  = bc % C3;
    const float* plane = g_qkv + (size_t)bc * HWS;
    float*       op    = g_dw  + (size_t)bc * HWS;

    float wr[9];
    #pragma unroll
    for (int i = 0; i < 9; i++) wr[i] = w[c * 9 + i];

    const int x  = blockIdx.x * 64 + threadIdx.x;
    const int yb = blockIdx.y * 32 + threadIdx.y * 8;

    float o[8];
    #pragma unroll
    for (int i = 0; i < 8; i++) o[i] = 0.f;

    #pragma unroll
    for (int i = -1; i <= 8; i++) {
        int r = yb + i;
        float l = 0.f, cv = 0.f, rv = 0.f;
        if (r >= 0 && r < HGT) {
            const float* row = plane + r * WID;
            cv = row[x];
            l  = (x > 0)   ? row[x - 1] : 0.f;
            rv = (x < 255) ? row[x + 1] : 0.f;
        }
        float h0 = wr[0] * l + wr[1] * cv + wr[2] * rv;  // contributes to out row r+1
        float h1 = wr[3] * l + wr[4] * cv + wr[5] * rv;  // out row r
        float h2 = wr[6] * l + wr[7] * cv + wr[8] * rv;  // out row r-1
        if (i - 1 >= 0 && i - 1 < 8) o[i - 1] += h2;
        if (i     >= 0 && i     < 8) o[i]     += h1;
        if (i + 1 >= 0 && i + 1 < 8) o[i + 1] += h0;
    }

    float ss = 0.f;
    #pragma unroll
    for (int j = 0; j < 8; j++) {
        op[(size_t)(yb + j) * WID + x] = o[j];
        ss += o[j] * o[j];
    }

    // per-block sumsq partial for q,k channels (c < 384)
    if (c < 2 * CC) {
        __shared__ float red[256];
        const int t = threadIdx.y * 64 + threadIdx.x;
        red[t] = ss;
        __syncthreads();
        #pragma unroll
        for (int off = 128; off > 0; off >>= 1) {
            if (t < off) red[t] += red[t + off];
            __syncthreads();
        }
        if (t == 0) g_sqp[bc][blockIdx.y * 4 + blockIdx.x] = red[0];
    }
}

// ---------------------------------------------------------------------------
// Reduce the 32 per-tile sumsq partials per (b, q/k channel). 1 warp/channel.
// ---------------------------------------------------------------------------
__global__ __launch_bounds__(32) void sumsq_reduce_kernel()
{
    const int idx = blockIdx.x;             // b * 384 + c
    const int b = idx / (2 * CC);
    const int c = idx % (2 * CC);
    float v = g_sqp[b * C3 + c][threadIdx.x];
    #pragma unroll
    for (int off = 16; off > 0; off >>= 1)
        v += __shfl_down_sync(0xffffffffu, v, off);
    if (threadIdx.x == 0) g_sq[idx] = v;
}

// ---------------------------------------------------------------------------
// Split-K partials of S = Q @ K^T per (b,h). grid (NCHUNK, BB*NH), block 256.
// v2: 64-px tiles, float4 smem loads, warp covers 8 q-rows x 4 k-rows.
// ---------------------------------------------------------------------------
__global__ __launch_bounds__(256) void qk_partial_kernel()
{
    const int chunk = blockIdx.x;
    const int bh    = blockIdx.y;
    const int b  = bh >> 2;
    const int hh = bh & 3;

    const float* qb = g_dw + ((size_t)b * C3 + hh * DD) * HWS + (size_t)chunk * CHL;
    const float* kb = qb + (size_t)CC * HWS;

    __shared__ float qs[DD][68];
    __shared__ float ks[DD][68];

    const int t = threadIdx.x;
    // warp-friendly patch mapping: within a warp, 8 distinct td, 4 distinct te
    const int td = ((t >> 2) & 15) * 3;          // q rows [td, td+2]
    const int te = ((t & 3) | ((t >> 6) << 2)) * 3; // k rows [te, te+2]

    float acc[3][3] = {{0.f,0.f,0.f},{0.f,0.f,0.f},{0.f,0.f,0.f}};

    for (int n0 = 0; n0 < CHL; n0 += 64) {
        #pragma unroll
        for (int i = 0; i < 3; i++) {
            int f  = t + i * 256;        // 0..767
            int cc = f >> 4;
            int c4 = (f & 15) << 2;
            *(float4*)&qs[cc][c4] = *(const float4*)(qb + (size_t)cc * HWS + n0 + c4);
            *(float4*)&ks[cc][c4] = *(const float4*)(kb + (size_t)cc * HWS + n0 + c4);
        }
        __syncthreads();

        #pragma unroll
        for (int n4 = 0; n4 < 16; n4++) {
            float4 qv[3], kv[3];
            #pragma unroll
            for (int i = 0; i < 3; i++) qv[i] = *(const float4*)&qs[td + i][n4 * 4];
            #pragma unroll
            for (int j = 0; j < 3; j++) kv[j] = *(const float4*)&ks[te + j][n4 * 4];
            #pragma unroll
            for (int i = 0; i < 3; i++)
                #pragma unroll
                for (int j = 0; j < 3; j++) {
                    acc[i][j] += qv[i].x * kv[j].x;
                    acc[i][j] += qv[i].y * kv[j].y;
                    acc[i][j] += qv[i].z * kv[j].z;
                    acc[i][j] += qv[i].w * kv[j].w;
                }
        }
        __syncthreads();
    }

    float* dst = g_part + ((size_t)chunk * (BB * NH) + bh) * (DD * DD);
    #pragma unroll
    for (int i = 0; i < 3; i++)
        #pragma unroll
        for (int j = 0; j < 3; j++)
            dst[(td + i) * DD + te + j] = acc[i][j];
}

// ---------------------------------------------------------------------------
// Reduce partials -> scale by temp/(||q|| ||k||) -> softmax -> build
// W2[b][o][h*48+e] = sum_d proj_w[o][h*48+d] * attn[d][e].
// ---------------------------------------------------------------------------
__global__ __launch_bounds__(192) void softmax_w2_kernel(
    const float* __restrict__ temp, const float* __restrict__ projw)
{
    const int bh = blockIdx.x;
    const int b  = bh >> 2;
    const int hh = bh & 3;
    const int t  = threadIdx.x;

    __shared__ float S[DD][DD];
    __shared__ float nq[DD], nk[DD];

    for (int i = t; i < DD * DD; i += 192) {
        float s = 0.f;
        for (int ch = 0; ch < NCHUNK; ch++)
            s += g_part[((size_t)ch * (BB * NH) + bh) * (DD * DD) + i];
        S[i / DD][i % DD] = s;
    }
    if (t < DD) {
        nq[t] = fmaxf(sqrtf(g_sq[b * 2 * CC + hh * DD + t]),      1e-12f);
        nk[t] = fmaxf(sqrtf(g_sq[b * 2 * CC + CC + hh * DD + t]), 1e-12f);
    }
    __syncthreads();

    const float tmp = temp[hh];
    for (int i = t; i < DD * DD; i += 192) {
        int d = i / DD, e = i % DD;
        S[d][e] = S[d][e] * tmp / (nq[d] * nk[e]);
    }
    __syncthreads();

    if (t < DD) {
        float mx = -1e30f;
        #pragma unroll
        for (int e = 0; e < DD; e++) mx = fmaxf(mx, S[t][e]);
        float sum = 0.f;
        #pragma unroll
        for (int e = 0; e < DD; e++) { float v = expf(S[t][e] - mx); S[t][e] = v; sum += v; }
        float inv = 1.f / sum;
        #pragma unroll
        for (int e = 0; e < DD; e++) S[t][e] *= inv;
    }
    __syncthreads();

    const int o = t;
    float pr[DD];
    #pragma unroll
    for (int d = 0; d < DD; d++) pr[d] = projw[o * CC + hh * DD + d];
    #pragma unroll 4
    for (int e = 0; e < DD; e++) {
        float s = 0.f;
        #pragma unroll
        for (int d = 0; d < DD; d++) s += pr[d] * S[d][e];
        g_w2[((size_t)b * CC + o) * CC + hh * DD + e] = s;
    }
}

// ---------------------------------------------------------------------------
extern "C" void kernel_launch(void* const* d_in, const int* in_sizes, int n_in,
                              void* d_out, int out_size)
{
    const float* x      = (const float*)d_in[0];   // [4,192,256,256]
    const float* qkv_w  = (const float*)d_in[1];   // [576,192]
    const float* dw_w   = (const float*)d_in[2];   // [576,1,3,3]
    const float* temp   = (const float*)d_in[3];   // [4,1,1]
    const float* proj_w = (const float*)d_in[4];   // [192,192]
    float* out = (float*)d_out;                    // [4,192,256,256]

    float *qkv_buf, *dw_buf, *w2_buf;
    cudaGetSymbolAddress((void**)&qkv_buf, g_qkv);
    cudaGetSymbolAddress((void**)&dw_buf,  g_dw);
    cudaGetSymbolAddress((void**)&w2_buf,  g_w2);

    // 1) qkv 1x1 conv: [576,192] @ [192,65536] per batch  (tf32 tensor cores)
    gemm_tf32_kernel<<<dim3(C3 / 64, HWS / 256, BB), 256>>>(
        qkv_w, x, qkv_buf, C3, HWS, CC,
        0L, (long)CC * HWS, (long)C3 * HWS);

    // 2) depthwise 3x3 (+ fused sumsq partials)
    dwconv_kernel<<<dim3(4, 8, BB * C3), dim3(64, 4)>>>(dw_w);

    // 3) finish ||q||^2, ||k||^2
    sumsq_reduce_kernel<<<BB * 2 * CC, 32>>>();

    // 4) split-K S = Q K^T partials
    qk_partial_kernel<<<dim3(NCHUNK, BB * NH), 256>>>();

    // 5) reduce + scale + softmax + W2 = proj_w @ blockdiag(attn)
    softmax_w2_kernel<<<BB * NH, 192>>>(temp, proj_w);

    // 6) fused (attn @ v) + proj: out = W2[192,192] @ v[192,65536] per batch
    gemm_tf32_kernel<<<dim3(CC / 64, HWS / 256, BB), 256>>>(
        w2_buf, dw_buf + (size_t)2 * CC * HWS, out, CC, HWS, CC,
        (long)CC * CC, (long)C3 * HWS, (long)CC * HWS);
}

// round 4
// speedup vs baseline: 2.0059x; 1.0500x over previous
#include <cuda_runtime.h>

// Problem constants
#define BB   4
#define CC   192
#define C3   576
#define HGT  256
#define WID  256
#define HWS  65536
#define NH   4
#define DD   48
#define NCHUNK 32
#define CHL  (HWS / NCHUNK)   // 2048

// Scratch (device globals: allocation-free per harness rules)
__device__ float g_qkv[(size_t)BB * C3 * HWS];   // 1x1 conv output
__device__ float g_dw [(size_t)BB * C3 * HWS];   // dwconv output
__device__ float g_sqp[BB * C3][32];             // per-block sumsq partials (q,k only)
__device__ float g_sq [BB * 2 * CC];             // sum-of-squares for q,k channels
__device__ float g_part[(size_t)NCHUNK * BB * NH * DD * DD]; // split-K partials of S
__device__ float g_w2 [BB * CC * CC];            // fused proj_w @ blockdiag(attn)

// ---------------------------------------------------------------------------
// tf32 helpers
// ---------------------------------------------------------------------------
__device__ __forceinline__ unsigned f2tf32(float f) {
    unsigned u;
    asm("cvt.rna.tf32.f32 %0, %1;" : "=r"(u) : "f"(f));
    return u;
}

__device__ __forceinline__ void mma_tf32(float c[4], const unsigned a[4], const unsigned b[2]) {
    asm volatile(
        "mma.sync.aligned.m16n8k8.row.col.f32.tf32.tf32.f32 "
        "{%0,%1,%2,%3}, {%4,%5,%6,%7}, {%8,%9}, {%0,%1,%2,%3};"
        : "+f"(c[0]), "+f"(c[1]), "+f"(c[2]), "+f"(c[3])
        : "r"(a[0]), "r"(a[1]), "r"(a[2]), "r"(a[3]), "r"(b[0]), "r"(b[1]));
}

// ---------------------------------------------------------------------------
// tf32 tensor-core GEMM v2: pipelined. C[M,N] = A[M,K] @ B[K,N], row-major,
// batch via grid.z. BM=64, BN=256, BK=16, 256 threads (8 warps of 32x64).
// 2-stage smem double buffer + register staging of next tile's LDGs.
// Requires M%64==0, N%256==0, K%16==0.
// ---------------------------------------------------------------------------
__global__ __launch_bounds__(256, 2) void gemm_tf32_kernel(
    const float* __restrict__ A, const float* __restrict__ B, float* __restrict__ C,
    int M, int N, int K, long sA, long sB, long sC)
{
    __shared__ unsigned As[2][16][64 + 4];   // [stage][k][m], stride 68 (==4 mod 32)
    __shared__ unsigned Bs[2][16][256 + 4];  // [stage][k][n], stride 260 (==4 mod 32)

    const float* Ab = A + (long)blockIdx.z * sA;
    const float* Bb = B + (long)blockIdx.z * sB;
    float*       Cb = C + (long)blockIdx.z * sC;

    const int m0 = blockIdx.x * 64;
    const int n0 = blockIdx.y * 256;
    const int t    = threadIdx.x;
    const int lane = t & 31;
    const int wid  = t >> 5;
    const int wm   = (wid & 1) * 32;
    const int wn   = (wid >> 1) * 64;
    const int g    = lane >> 2;
    const int tg   = lane & 3;

    float acc[2][8][4];
    #pragma unroll
    for (int mt = 0; mt < 2; mt++)
        #pragma unroll
        for (int nt = 0; nt < 8; nt++)
            #pragma unroll
            for (int i = 0; i < 4; i++) acc[mt][nt][i] = 0.f;

    // per-thread load coordinates
    const int am  = t >> 2;                // A row 0..63
    const int ak  = (t & 3) << 2;          // A col4: 0,4,8,12
    const int bn4 = (t & 63) << 2;         // B col: 0..252
    const int bkr = t >> 6;                // B row group 0..3

    const float* apt = Ab + (long)(m0 + am) * K + ak;
    const float* bpt = Bb + (long)bkr * N + n0 + bn4;
    const long  bstp = (long)4 * N;

    float4 pa;
    float4 pb[4];

    // prologue: LDG tile 0 into regs, cvt+STS into stage 0
    pa = *(const float4*)(apt);
    #pragma unroll
    for (int i = 0; i < 4; i++)
        pb[i] = *(const float4*)(bpt + i * bstp);

    {
        As[0][ak + 0][am] = f2tf32(pa.x);
        As[0][ak + 1][am] = f2tf32(pa.y);
        As[0][ak + 2][am] = f2tf32(pa.z);
        As[0][ak + 3][am] = f2tf32(pa.w);
        #pragma unroll
        for (int i = 0; i < 4; i++) {
            uint4 u;
            u.x = f2tf32(pb[i].x); u.y = f2tf32(pb[i].y);
            u.z = f2tf32(pb[i].z); u.w = f2tf32(pb[i].w);
            *(uint4*)&Bs[0][bkr + i * 4][bn4] = u;
        }
    }
    __syncthreads();

    const int NT = K >> 4;   // 12
    for (int kt = 0; kt < NT; kt++) {
        const int cur = kt & 1;
        const int nxt = cur ^ 1;

        // issue next tile's LDGs (latency hidden behind MMA compute)
        if (kt + 1 < NT) {
            const float* ap = apt + (kt + 1) * 16;
            const float* bp = bpt + (long)(kt + 1) * 16 * N;
            pa = *(const float4*)(ap);
            #pragma unroll
            for (int i = 0; i < 4; i++)
                pb[i] = *(const float4*)(bp + i * bstp);
        }

        // compute on current stage
        #pragma unroll
        for (int s = 0; s < 16; s += 8) {
            unsigned af[2][4], bf[8][2];
            #pragma unroll
            for (int mt = 0; mt < 2; mt++) {
                int mb = wm + mt * 16 + g;
                af[mt][0] = As[cur][s + tg][mb];
                af[mt][1] = As[cur][s + tg][mb + 8];
                af[mt][2] = As[cur][s + tg + 4][mb];
                af[mt][3] = As[cur][s + tg + 4][mb + 8];
            }
            #pragma unroll
            for (int nt = 0; nt < 8; nt++) {
                int nb = wn + nt * 8 + g;
                bf[nt][0] = Bs[cur][s + tg][nb];
                bf[nt][1] = Bs[cur][s + tg + 4][nb];
            }
            #pragma unroll
            for (int mt = 0; mt < 2; mt++)
                #pragma unroll
                for (int nt = 0; nt < 8; nt++)
                    mma_tf32(acc[mt][nt], af[mt], bf[nt]);
        }

        // store staged regs into the other smem stage
        if (kt + 1 < NT) {
            As[nxt][ak + 0][am] = f2tf32(pa.x);
            As[nxt][ak + 1][am] = f2tf32(pa.y);
            As[nxt][ak + 2][am] = f2tf32(pa.z);
            As[nxt][ak + 3][am] = f2tf32(pa.w);
            #pragma unroll
            for (int i = 0; i < 4; i++) {
                uint4 u;
                u.x = f2tf32(pb[i].x); u.y = f2tf32(pb[i].y);
                u.z = f2tf32(pb[i].z); u.w = f2tf32(pb[i].w);
                *(uint4*)&Bs[nxt][bkr + i * 4][bn4] = u;
            }
        }
        __syncthreads();
    }

    #pragma unroll
    for (int mt = 0; mt < 2; mt++) {
        #pragma unroll
        for (int nt = 0; nt < 8; nt++) {
            int row = m0 + wm + mt * 16 + g;
            int col = n0 + wn + nt * 8 + 2 * tg;
            float2 v0 = make_float2(acc[mt][nt][0], acc[mt][nt][1]);
            float2 v1 = make_float2(acc[mt][nt][2], acc[mt][nt][3]);
            *(float2*)(Cb + (long)row * N + col)       = v0;
            *(float2*)(Cb + (long)(row + 8) * N + col) = v1;
        }
    }
}

// ---------------------------------------------------------------------------
// Depthwise 3x3 conv v2: 8 outputs per thread (vertical sliding window).
// block (64,4) -> tile 64 wide x 32 rows. grid (4, 8, BB*C3).
// Also accumulates per-block sum-of-squares partials for q,k channels.
// ---------------------------------------------------------------------------
__global__ __launch_bounds__(256) void dwconv_kernel(const float* __restrict__ w)
{
    const int bc = blockIdx.z;          // b*576 + c
    const int c  = bc % C3;
    const float* plane = g_qkv + (size_t)bc * HWS;
    float*       op    = g_dw  + (size_t)bc * HWS;

    float wr[9];
    #pragma unroll
    for (int i = 0; i < 9; i++) wr[i] = w[c * 9 + i];

    const int x  = blockIdx.x * 64 + threadIdx.x;
    const int yb = blockIdx.y * 32 + threadIdx.y * 8;

    float o[8];
    #pragma unroll
    for (int i = 0; i < 8; i++) o[i] = 0.f;

    #pragma unroll
    for (int i = -1; i <= 8; i++) {
        int r = yb + i;
        float l = 0.f, cv = 0.f, rv = 0.f;
        if (r >= 0 && r < HGT) {
            const float* row = plane + r * WID;
            cv = row[x];
            l  = (x > 0)   ? row[x - 1] : 0.f;
            rv = (x < 255) ? row[x + 1] : 0.f;
        }
        float h0 = wr[0] * l + wr[1] * cv + wr[2] * rv;
        float h1 = wr[3] * l + wr[4] * cv + wr[5] * rv;
        float h2 = wr[6] * l + wr[7] * cv + wr[8] * rv;
        if (i - 1 >= 0 && i - 1 < 8) o[i - 1] += h2;
        if (i     >= 0 && i     < 8) o[i]     += h1;
        if (i + 1 >= 0 && i + 1 < 8) o[i + 1] += h0;
    }

    float ss = 0.f;
    #pragma unroll
    for (int j = 0; j < 8; j++) {
        op[(size_t)(yb + j) * WID + x] = o[j];
        ss += o[j] * o[j];
    }

    if (c < 2 * CC) {
        __shared__ float red[256];
        const int t = threadIdx.y * 64 + threadIdx.x;
        red[t] = ss;
        __syncthreads();
        #pragma unroll
        for (int off = 128; off > 0; off >>= 1) {
            if (t < off) red[t] += red[t + off];
            __syncthreads();
        }
        if (t == 0) g_sqp[bc][blockIdx.y * 4 + blockIdx.x] = red[0];
    }
}

// ---------------------------------------------------------------------------
// Reduce the 32 per-tile sumsq partials per (b, q/k channel). 1 warp/channel.
// ---------------------------------------------------------------------------
__global__ __launch_bounds__(32) void sumsq_reduce_kernel()
{
    const int idx = blockIdx.x;             // b * 384 + c
    const int b = idx / (2 * CC);
    const int c = idx % (2 * CC);
    float v = g_sqp[b * C3 + c][threadIdx.x];
    #pragma unroll
    for (int off = 16; off > 0; off >>= 1)
        v += __shfl_down_sync(0xffffffffu, v, off);
    if (threadIdx.x == 0) g_sq[idx] = v;
}

// ---------------------------------------------------------------------------
// Split-K partials of S = Q @ K^T per (b,h). grid (NCHUNK, BB*NH), block 256.
// ---------------------------------------------------------------------------
__global__ __launch_bounds__(256) void qk_partial_kernel()
{
    const int chunk = blockIdx.x;
    const int bh    = blockIdx.y;
    const int b  = bh >> 2;
    const int hh = bh & 3;

    const float* qb = g_dw + ((size_t)b * C3 + hh * DD) * HWS + (size_t)chunk * CHL;
    const float* kb = qb + (size_t)CC * HWS;

    __shared__ float qs[DD][68];
    __shared__ float ks[DD][68];

    const int t = threadIdx.x;
    const int td = ((t >> 2) & 15) * 3;
    const int te = ((t & 3) | ((t >> 6) << 2)) * 3;

    float acc[3][3] = {{0.f,0.f,0.f},{0.f,0.f,0.f},{0.f,0.f,0.f}};

    for (int n0 = 0; n0 < CHL; n0 += 64) {
        #pragma unroll
        for (int i = 0; i < 3; i++) {
            int f  = t + i * 256;
            int cc = f >> 4;
            int c4 = (f & 15) << 2;
            *(float4*)&qs[cc][c4] = *(const float4*)(qb + (size_t)cc * HWS + n0 + c4);
            *(float4*)&ks[cc][c4] = *(const float4*)(kb + (size_t)cc * HWS + n0 + c4);
        }
        __syncthreads();

        #pragma unroll
        for (int n4 = 0; n4 < 16; n4++) {
            float4 qv[3], kv[3];
            #pragma unroll
            for (int i = 0; i < 3; i++) qv[i] = *(const float4*)&qs[td + i][n4 * 4];
            #pragma unroll
            for (int j = 0; j < 3; j++) kv[j] = *(const float4*)&ks[te + j][n4 * 4];
            #pragma unroll
            for (int i = 0; i < 3; i++)
                #pragma unroll
                for (int j = 0; j < 3; j++) {
                    acc[i][j] += qv[i].x * kv[j].x;
                    acc[i][j] += qv[i].y * kv[j].y;
                    acc[i][j] += qv[i].z * kv[j].z;
                    acc[i][j] += qv[i].w * kv[j].w;
                }
        }
        __syncthreads();
    }

    float* dst = g_part + ((size_t)chunk * (BB * NH) + bh) * (DD * DD);
    #pragma unroll
    for (int i = 0; i < 3; i++)
        #pragma unroll
        for (int j = 0; j < 3; j++)
            dst[(td + i) * DD + te + j] = acc[i][j];
}

// ---------------------------------------------------------------------------
// Reduce partials -> scale by temp/(||q|| ||k||) -> softmax -> build
// W2[b][o][h*48+e] = sum_d proj_w[o][h*48+d] * attn[d][e].
// ---------------------------------------------------------------------------
__global__ __launch_bounds__(192) void softmax_w2_kernel(
    const float* __restrict__ temp, const float* __restrict__ projw)
{
    const int bh = blockIdx.x;
    const int b  = bh >> 2;
    const int hh = bh & 3;
    const int t  = threadIdx.x;

    __shared__ float S[DD][DD];
    __shared__ float nq[DD], nk[DD];

    for (int i = t; i < DD * DD; i += 192) {
        float s = 0.f;
        for (int ch = 0; ch < NCHUNK; ch++)
            s += g_part[((size_t)ch * (BB * NH) + bh) * (DD * DD) + i];
        S[i / DD][i % DD] = s;
    }
    if (t < DD) {
        nq[t] = fmaxf(sqrtf(g_sq[b * 2 * CC + hh * DD + t]),      1e-12f);
        nk[t] = fmaxf(sqrtf(g_sq[b * 2 * CC + CC + hh * DD + t]), 1e-12f);
    }
    __syncthreads();

    const float tmp = temp[hh];
    for (int i = t; i < DD * DD; i += 192) {
        int d = i / DD, e = i % DD;
        S[d][e] = S[d][e] * tmp / (nq[d] * nk[e]);
    }
    __syncthreads();

    if (t < DD) {
        float mx = -1e30f;
        #pragma unroll
        for (int e = 0; e < DD; e++) mx = fmaxf(mx, S[t][e]);
        float sum = 0.f;
        #pragma unroll
        for (int e = 0; e < DD; e++) { float v = expf(S[t][e] - mx); S[t][e] = v; sum += v; }
        float inv = 1.f / sum;
        #pragma unroll
        for (int e = 0; e < DD; e++) S[t][e] *= inv;
    }
    __syncthreads();

    const int o = t;
    float pr[DD];
    #pragma unroll
    for (int d = 0; d < DD; d++) pr[d] = projw[o * CC + hh * DD + d];
    #pragma unroll 4
    for (int e = 0; e < DD; e++) {
        float s = 0.f;
        #pragma unroll
        for (int d = 0; d < DD; d++) s += pr[d] * S[d][e];
        g_w2[((size_t)b * CC + o) * CC + hh * DD + e] = s;
    }
}

// ---------------------------------------------------------------------------
extern "C" void kernel_launch(void* const* d_in, const int* in_sizes, int n_in,
                              void* d_out, int out_size)
{
    const float* x      = (const float*)d_in[0];   // [4,192,256,256]
    const float* qkv_w  = (const float*)d_in[1];   // [576,192]
    const float* dw_w   = (const float*)d_in[2];   // [576,1,3,3]
    const float* temp   = (const float*)d_in[3];   // [4,1,1]
    const float* proj_w = (const float*)d_in[4];   // [192,192]
    float* out = (float*)d_out;                    // [4,192,256,256]

    float *qkv_buf, *dw_buf, *w2_buf;
    cudaGetSymbolAddress((void**)&qkv_buf, g_qkv);
    cudaGetSymbolAddress((void**)&dw_buf,  g_dw);
    cudaGetSymbolAddress((void**)&w2_buf,  g_w2);

    // 1) qkv 1x1 conv: [576,192] @ [192,65536] per batch  (tf32, pipelined)
    gemm_tf32_kernel<<<dim3(C3 / 64, HWS / 256, BB), 256>>>(
        qkv_w, x, qkv_buf, C3, HWS, CC,
        0L, (long)CC * HWS, (long)C3 * HWS);

    // 2) depthwise 3x3 (+ fused sumsq partials)
    dwconv_kernel<<<dim3(4, 8, BB * C3), dim3(64, 4)>>>(dw_w);

    // 3) finish ||q||^2, ||k||^2
    sumsq_reduce_kernel<<<BB * 2 * CC, 32>>>();

    // 4) split-K S = Q K^T partials
    qk_partial_kernel<<<dim3(NCHUNK, BB * NH), 256>>>();

    // 5) reduce + scale + softmax + W2 = proj_w @ blockdiag(attn)
    softmax_w2_kernel<<<BB * NH, 192>>>(temp, proj_w);

    // 6) fused (attn @ v) + proj: out = W2[192,192] @ v[192,65536] per batch
    gemm_tf32_kernel<<<dim3(CC / 64, HWS / 256, BB), 256>>>(
        w2_buf, dw_buf + (size_t)2 * CC * HWS, out, CC, HWS, CC,
        (long)CC * CC, (long)C3 * HWS, (long)CC * HWS);
}

// round 5
// speedup vs baseline: 2.0474x; 1.0207x over previous
#include <cuda_runtime.h>

// Problem constants
#define BB   4
#define CC   192
#define C3   576
#define HGT  256
#define WID  256
#define HWS  65536
#define NH   4
#define DD   48
#define NCHUNK 32
#define CHL  (HWS / NCHUNK)   // 2048
#define NPART (NCHUNK * 8)    // 256 split-K partial slots (8 warps per chunk)

// Scratch (device globals)
__device__ float g_qkv[(size_t)BB * C3 * HWS];
__device__ float g_dw [(size_t)BB * C3 * HWS];
__device__ float g_sqp[BB * C3][8];              // per-block sumsq partials (q,k)
__device__ float g_sq [BB * 2 * CC];
__device__ float g_part[(size_t)NPART * BB * NH * DD * DD];
__device__ float g_w2 [BB * CC * CC];

// ---------------------------------------------------------------------------
__device__ __forceinline__ unsigned f2tf32(float f) {
    unsigned u;
    asm("cvt.rna.tf32.f32 %0, %1;" : "=r"(u) : "f"(f));
    return u;
}

__device__ __forceinline__ void mma_tf32(float c[4], const unsigned a[4], const unsigned b[2]) {
    asm volatile(
        "mma.sync.aligned.m16n8k8.row.col.f32.tf32.tf32.f32 "
        "{%0,%1,%2,%3}, {%4,%5,%6,%7}, {%8,%9}, {%0,%1,%2,%3};"
        : "+f"(c[0]), "+f"(c[1]), "+f"(c[2]), "+f"(c[3])
        : "r"(a[0]), "r"(a[1]), "r"(a[2]), "r"(a[3]), "r"(b[0]), "r"(b[1]));
}

// ---------------------------------------------------------------------------
// tf32 tensor-core GEMM (pipelined): C[M,N] = A[M,K] @ B[K,N], batch grid.z.
// BM=64, BN=256, BK=16, 256 threads.
// ---------------------------------------------------------------------------
__global__ __launch_bounds__(256, 2) void gemm_tf32_kernel(
    const float* __restrict__ A, const float* __restrict__ B, float* __restrict__ C,
    int M, int N, int K, long sA, long sB, long sC)
{
    __shared__ unsigned As[2][16][64 + 4];
    __shared__ unsigned Bs[2][16][256 + 4];

    const float* Ab = A + (long)blockIdx.z * sA;
    const float* Bb = B + (long)blockIdx.z * sB;
    float*       Cb = C + (long)blockIdx.z * sC;

    const int m0 = blockIdx.x * 64;
    const int n0 = blockIdx.y * 256;
    const int t    = threadIdx.x;
    const int lane = t & 31;
    const int wid  = t >> 5;
    const int wm   = (wid & 1) * 32;
    const int wn   = (wid >> 1) * 64;
    const int g    = lane >> 2;
    const int tg   = lane & 3;

    float acc[2][8][4];
    #pragma unroll
    for (int mt = 0; mt < 2; mt++)
        #pragma unroll
        for (int nt = 0; nt < 8; nt++)
            #pragma unroll
            for (int i = 0; i < 4; i++) acc[mt][nt][i] = 0.f;

    const int am  = t >> 2;
    const int ak  = (t & 3) << 2;
    const int bn4 = (t & 63) << 2;
    const int bkr = t >> 6;

    const float* apt = Ab + (long)(m0 + am) * K + ak;
    const float* bpt = Bb + (long)bkr * N + n0 + bn4;
    const long  bstp = (long)4 * N;

    float4 pa;
    float4 pb[4];

    pa = *(const float4*)(apt);
    #pragma unroll
    for (int i = 0; i < 4; i++)
        pb[i] = *(const float4*)(bpt + i * bstp);

    {
        As[0][ak + 0][am] = f2tf32(pa.x);
        As[0][ak + 1][am] = f2tf32(pa.y);
        As[0][ak + 2][am] = f2tf32(pa.z);
        As[0][ak + 3][am] = f2tf32(pa.w);
        #pragma unroll
        for (int i = 0; i < 4; i++) {
            uint4 u;
            u.x = f2tf32(pb[i].x); u.y = f2tf32(pb[i].y);
            u.z = f2tf32(pb[i].z); u.w = f2tf32(pb[i].w);
            *(uint4*)&Bs[0][bkr + i * 4][bn4] = u;
        }
    }
    __syncthreads();

    const int NT = K >> 4;
    for (int kt = 0; kt < NT; kt++) {
        const int cur = kt & 1;
        const int nxt = cur ^ 1;

        if (kt + 1 < NT) {
            const float* ap = apt + (kt + 1) * 16;
            const float* bp = bpt + (long)(kt + 1) * 16 * N;
            pa = *(const float4*)(ap);
            #pragma unroll
            for (int i = 0; i < 4; i++)
                pb[i] = *(const float4*)(bp + i * bstp);
        }

        #pragma unroll
        for (int s = 0; s < 16; s += 8) {
            unsigned af[2][4], bf[8][2];
            #pragma unroll
            for (int mt = 0; mt < 2; mt++) {
                int mb = wm + mt * 16 + g;
                af[mt][0] = As[cur][s + tg][mb];
                af[mt][1] = As[cur][s + tg][mb + 8];
                af[mt][2] = As[cur][s + tg + 4][mb];
                af[mt][3] = As[cur][s + tg + 4][mb + 8];
            }
            #pragma unroll
            for (int nt = 0; nt < 8; nt++) {
                int nb = wn + nt * 8 + g;
                bf[nt][0] = Bs[cur][s + tg][nb];
                bf[nt][1] = Bs[cur][s + tg + 4][nb];
            }
            #pragma unroll
            for (int mt = 0; mt < 2; mt++)
                #pragma unroll
                for (int nt = 0; nt < 8; nt++)
                    mma_tf32(acc[mt][nt], af[mt], bf[nt]);
        }

        if (kt + 1 < NT) {
            As[nxt][ak + 0][am] = f2tf32(pa.x);
            As[nxt][ak + 1][am] = f2tf32(pa.y);
            As[nxt][ak + 2][am] = f2tf32(pa.z);
            As[nxt][ak + 3][am] = f2tf32(pa.w);
            #pragma unroll
            for (int i = 0; i < 4; i++) {
                uint4 u;
                u.x = f2tf32(pb[i].x); u.y = f2tf32(pb[i].y);
                u.z = f2tf32(pb[i].z); u.w = f2tf32(pb[i].w);
                *(uint4*)&Bs[nxt][bkr + i * 4][bn4] = u;
            }
        }
        __syncthreads();
    }

    #pragma unroll
    for (int mt = 0; mt < 2; mt++) {
        #pragma unroll
        for (int nt = 0; nt < 8; nt++) {
            int row = m0 + wm + mt * 16 + g;
            int col = n0 + wn + nt * 8 + 2 * tg;
            float2 v0 = make_float2(acc[mt][nt][0], acc[mt][nt][1]);
            float2 v1 = make_float2(acc[mt][nt][2], acc[mt][nt][3]);
            *(float2*)(Cb + (long)row * N + col)       = v0;
            *(float2*)(Cb + (long)(row + 8) * N + col) = v1;
        }
    }
}

// ---------------------------------------------------------------------------
// Depthwise 3x3 conv v3: 4x8 = 32 outputs per thread, float4 IO.
// block (64,4): x covers the full 256-px row, y covers 32 rows. grid (1,8,BB*C3).
// Fused per-block sumsq partial for q,k channels.
// ---------------------------------------------------------------------------
__global__ __launch_bounds__(256) void dwconv_kernel(const float* __restrict__ w)
{
    const int bc = blockIdx.z;
    const int c  = bc % C3;
    const float* plane = g_qkv + (size_t)bc * HWS;
    float*       op    = g_dw  + (size_t)bc * HWS;

    float wr[9];
    #pragma unroll
    for (int i = 0; i < 9; i++) wr[i] = w[c * 9 + i];

    const int x0 = threadIdx.x * 4;               // 0..252
    const int yb = blockIdx.y * 32 + threadIdx.y * 8;

    float o[8][4];
    #pragma unroll
    for (int i = 0; i < 8; i++)
        #pragma unroll
        for (int j = 0; j < 4; j++) o[i][j] = 0.f;

    #pragma unroll
    for (int i = -1; i <= 8; i++) {
        int r = yb + i;
        float4 c4 = make_float4(0.f, 0.f, 0.f, 0.f);
        float l = 0.f, rr = 0.f;
        if (r >= 0 && r < HGT) {
            const float* row = plane + r * WID;
            c4 = *(const float4*)(row + x0);
            l  = (x0 > 0)   ? row[x0 - 1] : 0.f;
            rr = (x0 < 252) ? row[x0 + 4] : 0.f;
        }
        float lf[4] = { l,    c4.x, c4.y, c4.z };
        float mf[4] = { c4.x, c4.y, c4.z, c4.w };
        float rf[4] = { c4.y, c4.z, c4.w, rr   };

        #pragma unroll
        for (int j = 0; j < 4; j++) {
            float h0 = wr[0] * lf[j] + wr[1] * mf[j] + wr[2] * rf[j];  // -> out row r+1
            float h1 = wr[3] * lf[j] + wr[4] * mf[j] + wr[5] * rf[j];  // -> out row r
            float h2 = wr[6] * lf[j] + wr[7] * mf[j] + wr[8] * rf[j];  // -> out row r-1
            if (i - 1 >= 0 && i - 1 < 8) o[i - 1][j] += h2;
            if (i     >= 0 && i     < 8) o[i][j]     += h1;
            if (i + 1 >= 0 && i + 1 < 8) o[i + 1][j] += h0;
        }
    }

    float ss = 0.f;
    #pragma unroll
    for (int i = 0; i < 8; i++) {
        float4 v = make_float4(o[i][0], o[i][1], o[i][2], o[i][3]);
        *(float4*)(op + (size_t)(yb + i) * WID + x0) = v;
        ss += v.x * v.x + v.y * v.y + v.z * v.z + v.w * v.w;
    }

    if (c < 2 * CC) {
        __shared__ float red[256];
        const int t = threadIdx.y * 64 + threadIdx.x;
        red[t] = ss;
        __syncthreads();
        #pragma unroll
        for (int off = 128; off > 0; off >>= 1) {
            if (t < off) red[t] += red[t + off];
            __syncthreads();
        }
        if (t == 0) g_sqp[bc][blockIdx.y] = red[0];
    }
}

// ---------------------------------------------------------------------------
// Reduce the 8 per-tile sumsq partials per (b, q/k channel).
// ---------------------------------------------------------------------------
__global__ __launch_bounds__(32) void sumsq_reduce_kernel()
{
    const int idx = blockIdx.x;             // b * 384 + c
    const int b = idx / (2 * CC);
    const int c = idx % (2 * CC);
    float v = (threadIdx.x < 8) ? g_sqp[b * C3 + c][threadIdx.x] : 0.f;
    #pragma unroll
    for (int off = 4; off > 0; off >>= 1)
        v += __shfl_down_sync(0xffffffffu, v, off);
    if (threadIdx.x == 0) g_sq[idx] = v;
}

// ---------------------------------------------------------------------------
// Split-K partials of S = Q @ K^T per (b,h) with tf32 MMA.
// grid (NCHUNK, BB*NH), 256 threads. Per 64-px smem tile, warp w computes the
// k8-slice s0=w*8 into its own full 48x48 accumulator; each warp writes an
// independent partial slot (chunk*8 + w). Deterministic (fixed split).
// ---------------------------------------------------------------------------
__global__ __launch_bounds__(256) void qk_partial_kernel()
{
    const int chunk = blockIdx.x;
    const int bh    = blockIdx.y;
    const int b  = bh >> 2;
    const int hh = bh & 3;

    const float* qb = g_dw + ((size_t)b * C3 + hh * DD) * HWS + (size_t)chunk * CHL;
    const float* kb = qb + (size_t)CC * HWS;

    __shared__ unsigned qs[DD][68];    // [channel d][pixel], tf32
    __shared__ unsigned ks[DD][68];    // [channel e][pixel], tf32

    const int t    = threadIdx.x;
    const int lane = t & 31;
    const int w    = t >> 5;
    const int g    = lane >> 2;
    const int tg   = lane & 3;
    const int s0   = w * 8;            // this warp's pixel sub-slice

    float acc[3][6][4];
    #pragma unroll
    for (int mt = 0; mt < 3; mt++)
        #pragma unroll
        for (int nt = 0; nt < 6; nt++)
            #pragma unroll
            for (int i = 0; i < 4; i++) acc[mt][nt][i] = 0.f;

    for (int n0 = 0; n0 < CHL; n0 += 64) {
        #pragma unroll
        for (int i = 0; i < 3; i++) {
            int f  = t + i * 256;          // 0..767 = 48 rows x 16 float4
            int cc = f >> 4;
            int c4 = (f & 15) << 2;
            float4 qv = *(const float4*)(qb + (size_t)cc * HWS + n0 + c4);
            float4 kv = *(const float4*)(kb + (size_t)cc * HWS + n0 + c4);
            uint4 uq, uk;
            uq.x = f2tf32(qv.x); uq.y = f2tf32(qv.y); uq.z = f2tf32(qv.z); uq.w = f2tf32(qv.w);
            uk.x = f2tf32(kv.x); uk.y = f2tf32(kv.y); uk.z = f2tf32(kv.z); uk.w = f2tf32(kv.w);
            *(uint4*)&qs[cc][c4] = uq;
            *(uint4*)&ks[cc][c4] = uk;
        }
        __syncthreads();

        unsigned af[3][4], bf[6][2];
        #pragma unroll
        for (int mt = 0; mt < 3; mt++) {
            int m = mt * 16 + g;
            af[mt][0] = qs[m][s0 + tg];
            af[mt][1] = qs[m + 8][s0 + tg];
            af[mt][2] = qs[m][s0 + tg + 4];
            af[mt][3] = qs[m + 8][s0 + tg + 4];
        }
        #pragma unroll
        for (int nt = 0; nt < 6; nt++) {
            int n = nt * 8 + g;
            bf[nt][0] = ks[n][s0 + tg];
            bf[nt][1] = ks[n][s0 + tg + 4];
        }
        #pragma unroll
        for (int mt = 0; mt < 3; mt++)
            #pragma unroll
            for (int nt = 0; nt < 6; nt++)
                mma_tf32(acc[mt][nt], af[mt], bf[nt]);
        __syncthreads();
    }

    float* dst = g_part + ((size_t)(chunk * 8 + w) * (BB * NH) + bh) * (DD * DD);
    #pragma unroll
    for (int mt = 0; mt < 3; mt++) {
        #pragma unroll
        for (int nt = 0; nt < 6; nt++) {
            int row = mt * 16 + g;
            int col = nt * 8 + 2 * tg;
            *(float2*)(dst + row * DD + col)       = make_float2(acc[mt][nt][0], acc[mt][nt][1]);
            *(float2*)(dst + (row + 8) * DD + col) = make_float2(acc[mt][nt][2], acc[mt][nt][3]);
        }
    }
}

// ---------------------------------------------------------------------------
// Reduce partials -> scale -> softmax -> W2 = proj_w @ blockdiag(attn).
// ---------------------------------------------------------------------------
__global__ __launch_bounds__(192) void softmax_w2_kernel(
    const float* __restrict__ temp, const float* __restrict__ projw)
{
    const int bh = blockIdx.x;
    const int b  = bh >> 2;
    const int hh = bh & 3;
    const int t  = threadIdx.x;

    __shared__ float S[DD][DD];
    __shared__ float nq[DD], nk[DD];

    for (int i = t; i < DD * DD; i += 192) {
        float s = 0.f;
        #pragma unroll 8
        for (int ch = 0; ch < NPART; ch++)
            s += g_part[((size_t)ch * (BB * NH) + bh) * (DD * DD) + i];
        S[i / DD][i % DD] = s;
    }
    if (t < DD) {
        nq[t] = fmaxf(sqrtf(g_sq[b * 2 * CC + hh * DD + t]),      1e-12f);
        nk[t] = fmaxf(sqrtf(g_sq[b * 2 * CC + CC + hh * DD + t]), 1e-12f);
    }
    __syncthreads();

    const float tmp = temp[hh];
    for (int i = t; i < DD * DD; i += 192) {
        int d = i / DD, e = i % DD;
        S[d][e] = S[d][e] * tmp / (nq[d] * nk[e]);
    }
    __syncthreads();

    if (t < DD) {
        float mx = -1e30f;
        #pragma unroll
        for (int e = 0; e < DD; e++) mx = fmaxf(mx, S[t][e]);
        float sum = 0.f;
        #pragma unroll
        for (int e = 0; e < DD; e++) { float v = expf(S[t][e] - mx); S[t][e] = v; sum += v; }
        float inv = 1.f / sum;
        #pragma unroll
        for (int e = 0; e < DD; e++) S[t][e] *= inv;
    }
    __syncthreads();

    const int o = t;
    float pr[DD];
    #pragma unroll
    for (int d = 0; d < DD; d++) pr[d] = projw[o * CC + hh * DD + d];
    #pragma unroll 4
    for (int e = 0; e < DD; e++) {
        float s = 0.f;
        #pragma unroll
        for (int d = 0; d < DD; d++) s += pr[d] * S[d][e];
        g_w2[((size_t)b * CC + o) * CC + hh * DD + e] = s;
    }
}

// ---------------------------------------------------------------------------
extern "C" void kernel_launch(void* const* d_in, const int* in_sizes, int n_in,
                              void* d_out, int out_size)
{
    const float* x      = (const float*)d_in[0];
    const float* qkv_w  = (const float*)d_in[1];
    const float* dw_w   = (const float*)d_in[2];
    const float* temp   = (const float*)d_in[3];
    const float* proj_w = (const float*)d_in[4];
    float* out = (float*)d_out;

    float *qkv_buf, *dw_buf, *w2_buf;
    cudaGetSymbolAddress((void**)&qkv_buf, g_qkv);
    cudaGetSymbolAddress((void**)&dw_buf,  g_dw);
    cudaGetSymbolAddress((void**)&w2_buf,  g_w2);

    // 1) qkv 1x1 conv (tf32, pipelined)
    gemm_tf32_kernel<<<dim3(C3 / 64, HWS / 256, BB), 256>>>(
        qkv_w, x, qkv_buf, C3, HWS, CC,
        0L, (long)CC * HWS, (long)C3 * HWS);

    // 2) depthwise 3x3 (+ fused sumsq partials), 32 px/thread
    dwconv_kernel<<<dim3(1, 8, BB * C3), dim3(64, 4)>>>(dw_w);

    // 3) finish ||q||^2, ||k||^2
    sumsq_reduce_kernel<<<BB * 2 * CC, 32>>>();

    // 4) split-K S = Q K^T partials (tf32 MMA)
    qk_partial_kernel<<<dim3(NCHUNK, BB * NH), 256>>>();

    // 5) reduce + scale + softmax + W2
    softmax_w2_kernel<<<BB * NH, 192>>>(temp, proj_w);

    // 6) fused (attn @ v) + proj (tf32, pipelined)
    gemm_tf32_kernel<<<dim3(CC / 64, HWS / 256, BB), 256>>>(
        w2_buf, dw_buf + (size_t)2 * CC * HWS, out, CC, HWS, CC,
        (long)CC * CC, (long)C3 * HWS, (long)CC * HWS);
}

// round 6
// speedup vs baseline: 2.1805x; 1.0650x over previous
#include <cuda_runtime.h>
#include <cuda_fp16.h>

// Problem constants
#define BB   4
#define CC   192
#define C3   576
#define HGT  256
#define WID  256
#define HWS  65536
#define NH   4
#define DD   48
#define NCHUNK 32
#define CHL  (HWS / NCHUNK)   // 2048
#define NPART (NCHUNK * 8)    // 256 split-K partial slots

// Scratch (device globals)
__device__ float g_qkv[(size_t)BB * C3 * HWS];
__device__ float g_dw [(size_t)BB * C3 * HWS];
__device__ float g_sqp[BB * C3][32];
__device__ float g_sq [BB * 2 * CC];
__device__ float g_part[(size_t)NPART * BB * NH * DD * DD];
__device__ float g_w2 [BB * CC * CC];

// ---------------------------------------------------------------------------
__device__ __forceinline__ unsigned f2tf32(float f) {
    unsigned u;
    asm("cvt.rna.tf32.f32 %0, %1;" : "=r"(u) : "f"(f));
    return u;
}

__device__ __forceinline__ unsigned pack_h2(float lo, float hi) {
    __half2 h = __halves2half2(__float2half_rn(lo), __float2half_rn(hi));
    return *(unsigned*)&h;
}

__device__ __forceinline__ void mma_tf32(float c[4], const unsigned a[4], const unsigned b[2]) {
    asm volatile(
        "mma.sync.aligned.m16n8k8.row.col.f32.tf32.tf32.f32 "
        "{%0,%1,%2,%3}, {%4,%5,%6,%7}, {%8,%9}, {%0,%1,%2,%3};"
        : "+f"(c[0]), "+f"(c[1]), "+f"(c[2]), "+f"(c[3])
        : "r"(a[0]), "r"(a[1]), "r"(a[2]), "r"(a[3]), "r"(b[0]), "r"(b[1]));
}

__device__ __forceinline__ void mma_fp16(float c[4], const unsigned a[4], const unsigned b[2]) {
    asm volatile(
        "mma.sync.aligned.m16n8k16.row.col.f32.f16.f16.f32 "
        "{%0,%1,%2,%3}, {%4,%5,%6,%7}, {%8,%9}, {%0,%1,%2,%3};"
        : "+f"(c[0]), "+f"(c[1]), "+f"(c[2]), "+f"(c[3])
        : "r"(a[0]), "r"(a[1]), "r"(a[2]), "r"(a[3]), "r"(b[0]), "r"(b[1]));
}

// ---------------------------------------------------------------------------
// fp16 tensor-core GEMM (pipelined): C[M,N] = A[M,K] @ B[K,N], batch grid.z.
// BM=64, BN=256, BK=16 (one m16n8k16 step), 256 threads, 8 warps of 32x64.
// k-pairs packed into b32 lanes (lo = even k). 2-stage smem double buffer.
// ---------------------------------------------------------------------------
__global__ __launch_bounds__(256, 2) void gemm_fp16_kernel(
    const float* __restrict__ A, const float* __restrict__ B, float* __restrict__ C,
    int M, int N, int K, long sA, long sB, long sC)
{
    __shared__ unsigned Ap[2][8][64 + 4];    // [stage][k2][m]
    __shared__ unsigned Bp[2][8][256 + 4];   // [stage][k2][n]

    const float* Ab = A + (long)blockIdx.z * sA;
    const float* Bb = B + (long)blockIdx.z * sB;
    float*       Cb = C + (long)blockIdx.z * sC;

    const int m0 = blockIdx.x * 64;
    const int n0 = blockIdx.y * 256;
    const int t    = threadIdx.x;
    const int lane = t & 31;
    const int wid  = t >> 5;
    const int wm   = (wid & 1) * 32;
    const int wn   = (wid >> 1) * 64;
    const int g    = lane >> 2;
    const int tg   = lane & 3;

    float acc[2][8][4];
    #pragma unroll
    for (int mt = 0; mt < 2; mt++)
        #pragma unroll
        for (int nt = 0; nt < 8; nt++)
            #pragma unroll
            for (int i = 0; i < 4; i++) acc[mt][nt][i] = 0.f;

    // load coordinates
    const int am  = t >> 2;                // A row 0..63
    const int ak  = (t & 3) << 2;          // A col: 0,4,8,12
    const int ak2 = ak >> 1;               // packed k2 base
    const int bn4 = (t & 63) << 2;         // B col 0..252
    const int bk2 = (t >> 6) << 1;         // packed k2 base: 0,2,4,6

    const float* apt = Ab + (long)(m0 + am) * K + ak;
    const float* bpt = Bb + (long)(bk2 * 2) * N + n0 + bn4;   // row = 2*bk2

    float4 pa;
    float4 pb[4];   // rows 2bk2, 2bk2+1, 2bk2+2, 2bk2+3

    pa = *(const float4*)(apt);
    #pragma unroll
    for (int i = 0; i < 4; i++)
        pb[i] = *(const float4*)(bpt + (long)i * N);

    {
        Ap[0][ak2 + 0][am] = pack_h2(pa.x, pa.y);
        Ap[0][ak2 + 1][am] = pack_h2(pa.z, pa.w);
        uint4 u0, u1;
        u0.x = pack_h2(pb[0].x, pb[1].x); u0.y = pack_h2(pb[0].y, pb[1].y);
        u0.z = pack_h2(pb[0].z, pb[1].z); u0.w = pack_h2(pb[0].w, pb[1].w);
        u1.x = pack_h2(pb[2].x, pb[3].x); u1.y = pack_h2(pb[2].y, pb[3].y);
        u1.z = pack_h2(pb[2].z, pb[3].z); u1.w = pack_h2(pb[2].w, pb[3].w);
        *(uint4*)&Bp[0][bk2][bn4]     = u0;
        *(uint4*)&Bp[0][bk2 + 1][bn4] = u1;
    }
    __syncthreads();

    const int NT = K >> 4;   // 12
    for (int kt = 0; kt < NT; kt++) {
        const int cur = kt & 1;
        const int nxt = cur ^ 1;

        if (kt + 1 < NT) {
            const float* ap = apt + (kt + 1) * 16;
            const float* bp = bpt + (long)(kt + 1) * 16 * N;
            pa = *(const float4*)(ap);
            #pragma unroll
            for (int i = 0; i < 4; i++)
                pb[i] = *(const float4*)(bp + (long)i * N);
        }

        // one m16n8k16 step over the whole BK=16 tile
        unsigned af[2][4], bf[8][2];
        #pragma unroll
        for (int mt = 0; mt < 2; mt++) {
            int mb = wm + mt * 16 + g;
            af[mt][0] = Ap[cur][tg][mb];
            af[mt][1] = Ap[cur][tg][mb + 8];
            af[mt][2] = Ap[cur][tg + 4][mb];
            af[mt][3] = Ap[cur][tg + 4][mb + 8];
        }
        #pragma unroll
        for (int nt = 0; nt < 8; nt++) {
            int nb = wn + nt * 8 + g;
            bf[nt][0] = Bp[cur][tg][nb];
            bf[nt][1] = Bp[cur][tg + 4][nb];
        }
        #pragma unroll
        for (int mt = 0; mt < 2; mt++)
            #pragma unroll
            for (int nt = 0; nt < 8; nt++)
                mma_fp16(acc[mt][nt], af[mt], bf[nt]);

        if (kt + 1 < NT) {
            Ap[nxt][ak2 + 0][am] = pack_h2(pa.x, pa.y);
            Ap[nxt][ak2 + 1][am] = pack_h2(pa.z, pa.w);
            uint4 u0, u1;
            u0.x = pack_h2(pb[0].x, pb[1].x); u0.y = pack_h2(pb[0].y, pb[1].y);
            u0.z = pack_h2(pb[0].z, pb[1].z); u0.w = pack_h2(pb[0].w, pb[1].w);
            u1.x = pack_h2(pb[2].x, pb[3].x); u1.y = pack_h2(pb[2].y, pb[3].y);
            u1.z = pack_h2(pb[2].z, pb[3].z); u1.w = pack_h2(pb[2].w, pb[3].w);
            *(uint4*)&Bp[nxt][bk2][bn4]     = u0;
            *(uint4*)&Bp[nxt][bk2 + 1][bn4] = u1;
        }
        __syncthreads();
    }

    #pragma unroll
    for (int mt = 0; mt < 2; mt++) {
        #pragma unroll
        for (int nt = 0; nt < 8; nt++) {
            int row = m0 + wm + mt * 16 + g;
            int col = n0 + wn + nt * 8 + 2 * tg;
            float2 v0 = make_float2(acc[mt][nt][0], acc[mt][nt][1]);
            float2 v1 = make_float2(acc[mt][nt][2], acc[mt][nt][3]);
            *(float2*)(Cb + (long)row * N + col)       = v0;
            *(float2*)(Cb + (long)(row + 8) * N + col) = v1;
        }
    }
}

// ---------------------------------------------------------------------------
// Depthwise 3x3 conv v2 (reverted, measured faster): 8 outputs per thread.
// block (64,4) -> tile 64 wide x 32 rows. grid (4, 8, BB*C3).
// Fused per-block sumsq partials for q,k channels.
// ---------------------------------------------------------------------------
__global__ __launch_bounds__(256) void dwconv_kernel(const float* __restrict__ w)
{
    const int bc = blockIdx.z;
    const int c  = bc % C3;
    const float* plane = g_qkv + (size_t)bc * HWS;
    float*       op    = g_dw  + (size_t)bc * HWS;

    float wr[9];
    #pragma unroll
    for (int i = 0; i < 9; i++) wr[i] = w[c * 9 + i];

    const int x  = blockIdx.x * 64 + threadIdx.x;
    const int yb = blockIdx.y * 32 + threadIdx.y * 8;

    float o[8];
    #pragma unroll
    for (int i = 0; i < 8; i++) o[i] = 0.f;

    #pragma unroll
    for (int i = -1; i <= 8; i++) {
        int r = yb + i;
        float l = 0.f, cv = 0.f, rv = 0.f;
        if (r >= 0 && r < HGT) {
            const float* row = plane + r * WID;
            cv = row[x];
            l  = (x > 0)   ? row[x - 1] : 0.f;
            rv = (x < 255) ? row[x + 1] : 0.f;
        }
        float h0 = wr[0] * l + wr[1] * cv + wr[2] * rv;
        float h1 = wr[3] * l + wr[4] * cv + wr[5] * rv;
        float h2 = wr[6] * l + wr[7] * cv + wr[8] * rv;
        if (i - 1 >= 0 && i - 1 < 8) o[i - 1] += h2;
        if (i     >= 0 && i     < 8) o[i]     += h1;
        if (i + 1 >= 0 && i + 1 < 8) o[i + 1] += h0;
    }

    float ss = 0.f;
    #pragma unroll
    for (int j = 0; j < 8; j++) {
        op[(size_t)(yb + j) * WID + x] = o[j];
        ss += o[j] * o[j];
    }

    if (c < 2 * CC) {
        __shared__ float red[256];
        const int t = threadIdx.y * 64 + threadIdx.x;
        red[t] = ss;
        __syncthreads();
        #pragma unroll
        for (int off = 128; off > 0; off >>= 1) {
            if (t < off) red[t] += red[t + off];
            __syncthreads();
        }
        if (t == 0) g_sqp[bc][blockIdx.y * 4 + blockIdx.x] = red[0];
    }
}

// ---------------------------------------------------------------------------
__global__ __launch_bounds__(32) void sumsq_reduce_kernel()
{
    const int idx = blockIdx.x;             // b * 384 + c
    const int b = idx / (2 * CC);
    const int c = idx % (2 * CC);
    float v = g_sqp[b * C3 + c][threadIdx.x];
    #pragma unroll
    for (int off = 16; off > 0; off >>= 1)
        v += __shfl_down_sync(0xffffffffu, v, off);
    if (threadIdx.x == 0) g_sq[idx] = v;
}

// ---------------------------------------------------------------------------
// Split-K partials of S = Q @ K^T per (b,h) with tf32 MMA.
// grid (NCHUNK, BB*NH), 256 threads; warp w handles k8-slice s0=w*8.
// ---------------------------------------------------------------------------
__global__ __launch_bounds__(256) void qk_partial_kernel()
{
    const int chunk = blockIdx.x;
    const int bh    = blockIdx.y;
    const int b  = bh >> 2;
    const int hh = bh & 3;

    const float* qb = g_dw + ((size_t)b * C3 + hh * DD) * HWS + (size_t)chunk * CHL;
    const float* kb = qb + (size_t)CC * HWS;

    __shared__ unsigned qs[DD][68];
    __shared__ unsigned ks[DD][68];

    const int t    = threadIdx.x;
    const int lane = t & 31;
    const int w    = t >> 5;
    const int g    = lane >> 2;
    const int tg   = lane & 3;
    const int s0   = w * 8;

    float acc[3][6][4];
    #pragma unroll
    for (int mt = 0; mt < 3; mt++)
        #pragma unroll
        for (int nt = 0; nt < 6; nt++)
            #pragma unroll
            for (int i = 0; i < 4; i++) acc[mt][nt][i] = 0.f;

    for (int n0 = 0; n0 < CHL; n0 += 64) {
        #pragma unroll
        for (int i = 0; i < 3; i++) {
            int f  = t + i * 256;
            int cc = f >> 4;
            int c4 = (f & 15) << 2;
            float4 qv = *(const float4*)(qb + (size_t)cc * HWS + n0 + c4);
            float4 kv = *(const float4*)(kb + (size_t)cc * HWS + n0 + c4);
            uint4 uq, uk;
            uq.x = f2tf32(qv.x); uq.y = f2tf32(qv.y); uq.z = f2tf32(qv.z); uq.w = f2tf32(qv.w);
            uk.x = f2tf32(kv.x); uk.y = f2tf32(kv.y); uk.z = f2tf32(kv.z); uk.w = f2tf32(kv.w);
            *(uint4*)&qs[cc][c4] = uq;
            *(uint4*)&ks[cc][c4] = uk;
        }
        __syncthreads();

        unsigned af[3][4], bf[6][2];
        #pragma unroll
        for (int mt = 0; mt < 3; mt++) {
            int m = mt * 16 + g;
            af[mt][0] = qs[m][s0 + tg];
            af[mt][1] = qs[m + 8][s0 + tg];
            af[mt][2] = qs[m][s0 + tg + 4];
            af[mt][3] = qs[m + 8][s0 + tg + 4];
        }
        #pragma unroll
        for (int nt = 0; nt < 6; nt++) {
            int n = nt * 8 + g;
            bf[nt][0] = ks[n][s0 + tg];
            bf[nt][1] = ks[n][s0 + tg + 4];
        }
        #pragma unroll
        for (int mt = 0; mt < 3; mt++)
            #pragma unroll
            for (int nt = 0; nt < 6; nt++)
                mma_tf32(acc[mt][nt], af[mt], bf[nt]);
        __syncthreads();
    }

    float* dst = g_part + ((size_t)(chunk * 8 + w) * (BB * NH) + bh) * (DD * DD);
    #pragma unroll
    for (int mt = 0; mt < 3; mt++) {
        #pragma unroll
        for (int nt = 0; nt < 6; nt++) {
            int row = mt * 16 + g;
            int col = nt * 8 + 2 * tg;
            *(float2*)(dst + row * DD + col)       = make_float2(acc[mt][nt][0], acc[mt][nt][1]);
            *(float2*)(dst + (row + 8) * DD + col) = make_float2(acc[mt][nt][2], acc[mt][nt][3]);
        }
    }
}

// ---------------------------------------------------------------------------
// Reduce partials -> scale -> softmax -> W2 = proj_w @ blockdiag(attn).
// ---------------------------------------------------------------------------
__global__ __launch_bounds__(192) void softmax_w2_kernel(
    const float* __restrict__ temp, const float* __restrict__ projw)
{
    const int bh = blockIdx.x;
    const int b  = bh >> 2;
    const int hh = bh & 3;
    const int t  = threadIdx.x;

    __shared__ float S[DD][DD];
    __shared__ float nq[DD], nk[DD];

    for (int i = t; i < DD * DD; i += 192) {
        float s = 0.f;
        #pragma unroll 8
        for (int ch = 0; ch < NPART; ch++)
            s += g_part[((size_t)ch * (BB * NH) + bh) * (DD * DD) + i];
        S[i / DD][i % DD] = s;
    }
    if (t < DD) {
        nq[t] = fmaxf(sqrtf(g_sq[b * 2 * CC + hh * DD + t]),      1e-12f);
        nk[t] = fmaxf(sqrtf(g_sq[b * 2 * CC + CC + hh * DD + t]), 1e-12f);
    }
    __syncthreads();

    const float tmp = temp[hh];
    for (int i = t; i < DD * DD; i += 192) {
        int d = i / DD, e = i % DD;
        S[d][e] = S[d][e] * tmp / (nq[d] * nk[e]);
    }
    __syncthreads();

    if (t < DD) {
        float mx = -1e30f;
        #pragma unroll
        for (int e = 0; e < DD; e++) mx = fmaxf(mx, S[t][e]);
        float sum = 0.f;
        #pragma unroll
        for (int e = 0; e < DD; e++) { float v = expf(S[t][e] - mx); S[t][e] = v; sum += v; }
        float inv = 1.f / sum;
        #pragma unroll
        for (int e = 0; e < DD; e++) S[t][e] *= inv;
    }
    __syncthreads();

    const int o = t;
    float pr[DD];
    #pragma unroll
    for (int d = 0; d < DD; d++) pr[d] = projw[o * CC + hh * DD + d];
    #pragma unroll 4
    for (int e = 0; e < DD; e++) {
        float s = 0.f;
        #pragma unroll
        for (int d = 0; d < DD; d++) s += pr[d] * S[d][e];
        g_w2[((size_t)b * CC + o) * CC + hh * DD + e] = s;
    }
}

// ---------------------------------------------------------------------------
extern "C" void kernel_launch(void* const* d_in, const int* in_sizes, int n_in,
                              void* d_out, int out_size)
{
    const float* x      = (const float*)d_in[0];
    const float* qkv_w  = (const float*)d_in[1];
    const float* dw_w   = (const float*)d_in[2];
    const float* temp   = (const float*)d_in[3];
    const float* proj_w = (const float*)d_in[4];
    float* out = (float*)d_out;

    float *qkv_buf, *dw_buf, *w2_buf;
    cudaGetSymbolAddress((void**)&qkv_buf, g_qkv);
    cudaGetSymbolAddress((void**)&dw_buf,  g_dw);
    cudaGetSymbolAddress((void**)&w2_buf,  g_w2);

    // 1) qkv 1x1 conv (fp16 tensor cores, pipelined)
    gemm_fp16_kernel<<<dim3(C3 / 64, HWS / 256, BB), 256>>>(
        qkv_w, x, qkv_buf, C3, HWS, CC,
        0L, (long)CC * HWS, (long)C3 * HWS);

    // 2) depthwise 3x3 (+ fused sumsq partials)
    dwconv_kernel<<<dim3(4, 8, BB * C3), dim3(64, 4)>>>(dw_w);

    // 3) finish ||q||^2, ||k||^2
    sumsq_reduce_kernel<<<BB * 2 * CC, 32>>>();

    // 4) split-K S = Q K^T partials (tf32 MMA)
    qk_partial_kernel<<<dim3(NCHUNK, BB * NH), 256>>>();

    // 5) reduce + scale + softmax + W2
    softmax_w2_kernel<<<BB * NH, 192>>>(temp, proj_w);

    // 6) fused (attn @ v) + proj (fp16 tensor cores, pipelined)
    gemm_fp16_kernel<<<dim3(CC / 64, HWS / 256, BB), 256>>>(
        w2_buf, dw_buf + (size_t)2 * CC * HWS, out, CC, HWS, CC,
        (long)CC * CC, (long)C3 * HWS, (long)CC * HWS);
}